// round 13
// baseline (speedup 1.0000x reference)
#include <cuda_runtime.h>
#include <math.h>

#define N_MAX 16384
#define F_MAX 256
#define E_MAX 524288
#define PRE_BLOCKS 148

// ---------------- scratch (device globals: no allocation allowed) ----------------
__device__ __align__(16) float g_bufH[N_MAX * F_MAX];   // Hs = h * dinv[row]
__device__ __align__(16) float g_bufG0[N_MAX * F_MAX];  // agg ping
__device__ __align__(16) float g_bufG1[N_MAX * F_MAX];  // agg pong
__device__ float g_dinv[N_MAX];
__device__ int   g_cin[N_MAX];
__device__ int   g_rowptr[N_MAX + 1];
__device__ int   g_fill[N_MAX];
__device__ int   g_csr[E_MAX];
__device__ float g_sum[F_MAX], g_sumsq[F_MAX];
__device__ float g_scale[F_MAX], g_shift[F_MAX];
__device__ unsigned g_ticket;
__device__ unsigned g_bar;   // zero-init; reset by GEMM launches

// ---------------- fused preamble ----------------
__device__ __forceinline__ void gbar(unsigned target) {
    __syncthreads();
    if (threadIdx.x == 0) {
        __threadfence();
        atomicAdd(&g_bar, 1u);
        while (*(volatile unsigned*)&g_bar < target) __nanosleep(64);
        __threadfence();
    }
    __syncthreads();
}

__device__ __forceinline__ void edge_sd_z(const void* ei, int z, int e, int E,
                                          int& s, int& d) {
    if (z) {
        const long long* p = (const long long*)ei;
        s = (int)p[e];
        d = (int)p[(long long)E + e];
    } else {
        const int* p = (const int*)ei;
        s = p[e];
        d = p[E + e];
    }
}

__global__ void k_pre(const void* __restrict__ ei, int N, int E) {
    const int* eip = (const int*)ei;
    int z = 1;
#pragma unroll
    for (int t = 0; t < 32; t++) z &= (eip[2 * t + 1] == 0);

    int tid = threadIdx.x;
    int gt = blockIdx.x * blockDim.x + tid;
    int nthr = gridDim.x * blockDim.x;

    for (int i = gt; i < N; i += nthr) { g_cin[i] = 0; g_fill[i] = 0; }
    if (gt < F_MAX) { g_sum[gt] = 0.0f; g_sumsq[gt] = 0.0f; }
    if (gt == 0) g_ticket = 0;
    gbar(1 * PRE_BLOCKS);

    for (int e = gt; e < E; e += nthr) {
        int s, d;
        edge_sd_z(ei, z, e, E, s, d);
        atomicAdd(&g_cin[d], 1);
    }
    gbar(2 * PRE_BLOCKS);

    if (blockIdx.x == 0) {
        __shared__ int wsum[8];
        int chunk = (N + 255) >> 8;
        int t0 = tid * chunk, t1 = min(N, t0 + chunk);
        int s = 0;
        for (int i = t0; i < t1; i++) {
            int c = g_cin[i];
            g_dinv[i] = rsqrtf((float)c + 1.0f);
            s += c;
        }
        int lane = tid & 31, wid = tid >> 5;
        int v = s;
#pragma unroll
        for (int o = 1; o < 32; o <<= 1) {
            int u = __shfl_up_sync(0xFFFFFFFFu, v, o);
            if (lane >= o) v += u;
        }
        if (lane == 31) wsum[wid] = v;
        __syncthreads();
        if (wid == 0 && lane < 8) {
            int w = wsum[lane];
#pragma unroll
            for (int o = 1; o < 8; o <<= 1) {
                int u = __shfl_up_sync(0xFFu, w, o);
                if (lane >= o) w += u;
            }
            wsum[lane] = w;
        }
        __syncthreads();
        int run = v - s + (wid > 0 ? wsum[wid - 1] : 0);
        for (int i = t0; i < t1; i++) {
            g_rowptr[i] = run;
            run += g_cin[i];
        }
        if (t0 < N && t1 == N) g_rowptr[N] = run;
    }
    gbar(3 * PRE_BLOCKS);

    for (int e = gt; e < E; e += nthr) {
        int s, d;
        edge_sd_z(ei, z, e, E, s, d);
        int pos = g_rowptr[d] + atomicAdd(&g_fill[d], 1);
        g_csr[pos] = s;
    }
}

// ---------------- GEMM 128x64 tile, 8x8 micro, 128 threads, double-buffered ----
// A k-reads unguarded in k (Bs rows beyond K are zeroed; buffers oversized).
__global__ __launch_bounds__(128) void k_gemm128(
        const float* __restrict__ A, const float* __restrict__ B,
        float* __restrict__ Hs,
        int N, int K, int M, int Kp, int Mp, int transform) {
    if (threadIdx.x == 0 && blockIdx.x == 0 && blockIdx.y == 0) g_bar = 0;
    __shared__ __align__(16) float As[2][16][132];
    __shared__ __align__(16) float Bs[2][16][68];
    int tid = threadIdx.x;            // 128 threads
    int tx = tid & 7, ty = tid >> 3;  // 8 x 16
    int row0 = blockIdx.y * 128, col0 = blockIdx.x * 64;
    float acc[8][8] = {};

    int T = (K + 15) >> 4;

    // A prefetch: thread covers row ar = tid, all 16 k (4 float4)
    int ar = tid;
    int agr = row0 + ar;
    // B prefetch: 2 float4 per thread; 16x64 = 256 float4
    int bidx0 = tid * 2;
    int br0 = bidx0 >> 4, bc0 = (bidx0 & 15) * 4;
    int br1 = (bidx0 + 1) >> 4, bc1 = ((bidx0 + 1) & 15) * 4;

    float4 pa[4];
    float pb0[4], pb1[4];

#define PREFETCH(t)                                                               \
    {                                                                             \
        int k0 = (t) << 4;                                                        \
        if (agr < N) {                                                            \
            const float* arow = A + (size_t)agr * Kp + k0;                        \
            pa[0] = *(const float4*)(arow + 0);                                   \
            pa[1] = *(const float4*)(arow + 4);                                   \
            pa[2] = *(const float4*)(arow + 8);                                   \
            pa[3] = *(const float4*)(arow + 12);                                  \
            if (transform) {                                                      \
                _Pragma("unroll")                                                 \
                for (int q = 0; q < 4; q++) {                                     \
                    int kb = k0 + q * 4;                                          \
                    pa[q].x = fmaf(fmaxf(pa[q].x, 0.0f), g_scale[kb + 0], g_shift[kb + 0]); \
                    pa[q].y = fmaf(fmaxf(pa[q].y, 0.0f), g_scale[kb + 1], g_shift[kb + 1]); \
                    pa[q].z = fmaf(fmaxf(pa[q].z, 0.0f), g_scale[kb + 2], g_shift[kb + 2]); \
                    pa[q].w = fmaf(fmaxf(pa[q].w, 0.0f), g_scale[kb + 3], g_shift[kb + 3]); \
                }                                                                 \
            }                                                                     \
        } else {                                                                  \
            pa[0] = pa[1] = pa[2] = pa[3] = make_float4(0, 0, 0, 0);              \
        }                                                                         \
        int gk0 = k0 + br0, gk1 = k0 + br1;                                       \
        _Pragma("unroll")                                                         \
        for (int i = 0; i < 4; i++) {                                             \
            int gc0 = col0 + bc0 + i, gc1 = col0 + bc1 + i;                       \
            pb0[i] = (gk0 < K && gc0 < M) ? B[(size_t)gk0 * M + gc0] : 0.0f;      \
            pb1[i] = (gk1 < K && gc1 < M) ? B[(size_t)gk1 * M + gc1] : 0.0f;      \
        }                                                                         \
    }

#define STORE(buf)                                                                \
    {                                                                             \
        _Pragma("unroll")                                                         \
        for (int q = 0; q < 4; q++) {                                             \
            As[buf][q * 4 + 0][ar] = pa[q].x;                                     \
            As[buf][q * 4 + 1][ar] = pa[q].y;                                     \
            As[buf][q * 4 + 2][ar] = pa[q].z;                                     \
            As[buf][q * 4 + 3][ar] = pa[q].w;                                     \
        }                                                                         \
        *(float4*)&Bs[buf][br0][bc0] = make_float4(pb0[0], pb0[1], pb0[2], pb0[3]); \
        *(float4*)&Bs[buf][br1][bc1] = make_float4(pb1[0], pb1[1], pb1[2], pb1[3]); \
    }

    PREFETCH(0)
    STORE(0)
    __syncthreads();

    for (int t = 0; t < T; t++) {
        int cur = t & 1;
        bool havenext = (t + 1 < T);
        if (havenext) PREFETCH(t + 1)
#pragma unroll
        for (int kk = 0; kk < 16; kk++) {
            float4 a0 = *(const float4*)&As[cur][kk][ty * 8];
            float4 a1 = *(const float4*)&As[cur][kk][ty * 8 + 4];
            float4 b0 = *(const float4*)&Bs[cur][kk][tx * 8];
            float4 b1 = *(const float4*)&Bs[cur][kk][tx * 8 + 4];
            float a[8] = {a0.x, a0.y, a0.z, a0.w, a1.x, a1.y, a1.z, a1.w};
            float bb[8] = {b0.x, b0.y, b0.z, b0.w, b1.x, b1.y, b1.z, b1.w};
#pragma unroll
            for (int i = 0; i < 8; i++)
#pragma unroll
                for (int j = 0; j < 8; j++)
                    acc[i][j] = fmaf(a[i], bb[j], acc[i][j]);
        }
        if (havenext) {
            STORE(cur ^ 1)
            __syncthreads();
        }
    }
#pragma unroll
    for (int i = 0; i < 8; i++) {
        int gr = row0 + ty * 8 + i;
        if (gr >= N) continue;
        float dd = g_dinv[gr];
#pragma unroll
        for (int j = 0; j < 8; j++) {
            int gc = col0 + tx * 8 + j;
            if (gc < Mp)
                Hs[(size_t)gr * Mp + gc] = (gc < M) ? acc[i][j] * dd : 0.0f;
        }
    }
#undef PREFETCH
#undef STORE
}

// ---------------- GEMM 64x64 tile (4x4 micro) ----------------------------------
__global__ void k_gemm64(const float* __restrict__ A, const float* __restrict__ B,
                         float* __restrict__ Hs,
                         int N, int K, int M, int Kp, int Mp, int transform) {
    if (threadIdx.x == 0 && blockIdx.x == 0 && blockIdx.y == 0) g_bar = 0;
    __shared__ __align__(16) float As[16][68];
    __shared__ __align__(16) float Bs[16][68];
    int tid = threadIdx.x;
    int tx = tid & 15, ty = tid >> 4;
    int row0 = blockIdx.y * 64, col0 = blockIdx.x * 64;
    float acc[4][4] = {};

    for (int k0 = 0; k0 < K; k0 += 16) {
        {
            int r  = tid >> 2;
            int c4 = (tid & 3) * 4;
            int gr = row0 + r;
#pragma unroll
            for (int i = 0; i < 4; i++) {
                int gk = k0 + c4 + i;
                float v = 0.0f;
                if (gr < N && gk < K) {
                    v = A[(size_t)gr * Kp + gk];
                    if (transform) v = fmaf(fmaxf(v, 0.0f), g_scale[gk], g_shift[gk]);
                }
                As[c4 + i][r] = v;
            }
        }
        {
            int lin = tid * 4;
            int r = lin >> 6;
            int c = lin & 63;
            int gk = k0 + r;
#pragma unroll
            for (int i = 0; i < 4; i++) {
                int gc = col0 + c + i;
                Bs[r][c + i] = (gk < K && gc < M) ? B[(size_t)gk * M + gc] : 0.0f;
            }
        }
        __syncthreads();
#pragma unroll
        for (int kk = 0; kk < 16; kk++) {
            float4 a4 = *(const float4*)&As[kk][ty * 4];
            float4 b4 = *(const float4*)&Bs[kk][tx * 4];
            float a[4] = {a4.x, a4.y, a4.z, a4.w};
            float bb[4] = {b4.x, b4.y, b4.z, b4.w};
#pragma unroll
            for (int i = 0; i < 4; i++)
#pragma unroll
                for (int j = 0; j < 4; j++)
                    acc[i][j] = fmaf(a[i], bb[j], acc[i][j]);
        }
        __syncthreads();
    }
#pragma unroll
    for (int i = 0; i < 4; i++) {
        int gr = row0 + ty * 4 + i;
        if (gr >= N) continue;
        float dd = g_dinv[gr];
#pragma unroll
        for (int j = 0; j < 4; j++) {
            int gc = col0 + tx * 4 + j;
            if (gc < Mp)
                Hs[(size_t)gr * Mp + gc] = (gc < M) ? acc[i][j] * dd : 0.0f;
        }
    }
}

// ---------------- coalesced CSR pull, sub-warp packed --------------------------
__global__ void k_pull(const float* __restrict__ Hs, const float* __restrict__ bias,
                       float* __restrict__ G, float* __restrict__ OUT,
                       int N, int M, int Mp, int nch4, int ngroups, int lg2gsz,
                       int mode,
                       const float* __restrict__ gam, const float* __restrict__ bet) {
    __shared__ float sm_s[F_MAX], sm_q[F_MAX];
    int tid = threadIdx.x;
    if (mode == 1) {
        for (int f = tid; f < F_MAX; f += blockDim.x) { sm_s[f] = 0.0f; sm_q[f] = 0.0f; }
        __syncthreads();
    }
    int gsz = 1 << lg2gsz;
    int epw = 32 >> lg2gsz;
    int lane = tid & 31;
    int sub = lane >> lg2gsz;
    int gw = (blockIdx.x * blockDim.x + tid) >> 5;
    int nw = (gridDim.x * blockDim.x) >> 5;
    int grp = (ngroups > 1) ? (gw % ngroups) : 0;
    int c = (lane & (gsz - 1)) + (grp << 5);
    bool act = c < nch4;
    int f0 = c << 2;
    float4 b4 = make_float4(0, 0, 0, 0);
    if (act) {
        b4.x = (f0 + 0 < M) ? bias[f0 + 0] : 0.0f;
        b4.y = (f0 + 1 < M) ? bias[f0 + 1] : 0.0f;
        b4.z = (f0 + 2 < M) ? bias[f0 + 2] : 0.0f;
        b4.w = (f0 + 3 < M) ? bias[f0 + 3] : 0.0f;
    }
    int wbase = gw / ngroups;
    int wstride = nw / ngroups;
    float4 ls = make_float4(0, 0, 0, 0), lq = make_float4(0, 0, 0, 0);

    for (int w = wbase; w * epw < N; w += wstride) {
        int d = w * epw + sub;
        bool vd = (d < N) && act;
        int beg = 0, end = 0;
        float dd = 0.0f;
        float4 acc = make_float4(0, 0, 0, 0);
        if (vd) {
            beg = g_rowptr[d];
            end = g_rowptr[d + 1];
            dd = g_dinv[d];
            acc = ((const float4*)(Hs + (size_t)d * Mp))[c];
        }
        int e = beg;
        for (; e + 7 < end; e += 8) {
            int s0 = g_csr[e], s1 = g_csr[e + 1], s2 = g_csr[e + 2], s3 = g_csr[e + 3];
            int s4 = g_csr[e + 4], s5 = g_csr[e + 5], s6 = g_csr[e + 6], s7 = g_csr[e + 7];
            float4 v0 = ((const float4*)(Hs + (size_t)s0 * Mp))[c];
            float4 v1 = ((const float4*)(Hs + (size_t)s1 * Mp))[c];
            float4 v2 = ((const float4*)(Hs + (size_t)s2 * Mp))[c];
            float4 v3 = ((const float4*)(Hs + (size_t)s3 * Mp))[c];
            float4 v4 = ((const float4*)(Hs + (size_t)s4 * Mp))[c];
            float4 v5 = ((const float4*)(Hs + (size_t)s5 * Mp))[c];
            float4 v6 = ((const float4*)(Hs + (size_t)s6 * Mp))[c];
            float4 v7 = ((const float4*)(Hs + (size_t)s7 * Mp))[c];
            acc.x += ((v0.x + v1.x) + (v2.x + v3.x)) + ((v4.x + v5.x) + (v6.x + v7.x));
            acc.y += ((v0.y + v1.y) + (v2.y + v3.y)) + ((v4.y + v5.y) + (v6.y + v7.y));
            acc.z += ((v0.z + v1.z) + (v2.z + v3.z)) + ((v4.z + v5.z) + (v6.z + v7.z));
            acc.w += ((v0.w + v1.w) + (v2.w + v3.w)) + ((v4.w + v5.w) + (v6.w + v7.w));
        }
        for (; e + 1 < end; e += 2) {
            int s0 = g_csr[e], s1 = g_csr[e + 1];
            float4 v0 = ((const float4*)(Hs + (size_t)s0 * Mp))[c];
            float4 v1 = ((const float4*)(Hs + (size_t)s1 * Mp))[c];
            acc.x += v0.x + v1.x; acc.y += v0.y + v1.y;
            acc.z += v0.z + v1.z; acc.w += v0.w + v1.w;
        }
        if (e < end) {
            int s0 = g_csr[e];
            float4 v0 = ((const float4*)(Hs + (size_t)s0 * Mp))[c];
            acc.x += v0.x; acc.y += v0.y; acc.z += v0.z; acc.w += v0.w;
        }
        float4 o;
        o.x = fmaf(dd, acc.x, b4.x);
        o.y = fmaf(dd, acc.y, b4.y);
        o.z = fmaf(dd, acc.z, b4.z);
        o.w = fmaf(dd, acc.w, b4.w);

        if (mode == 1) {
            if (vd) {
                ((float4*)(G + (size_t)d * Mp))[c] = o;
                float rx = fmaxf(o.x, 0.0f), ry = fmaxf(o.y, 0.0f);
                float rz = fmaxf(o.z, 0.0f), rw = fmaxf(o.w, 0.0f);
                ls.x += rx; ls.y += ry; ls.z += rz; ls.w += rw;
                lq.x += rx * rx; lq.y += ry * ry; lq.z += rz * rz; lq.w += rw * rw;
            }
        } else {
            bool vx = vd && (f0 + 0 < M), vy = vd && (f0 + 1 < M);
            bool vz = vd && (f0 + 2 < M), vw = vd && (f0 + 3 < M);
            float m = fmaxf(fmaxf(vx ? o.x : -1e30f, vy ? o.y : -1e30f),
                            fmaxf(vz ? o.z : -1e30f, vw ? o.w : -1e30f));
            for (int off = gsz >> 1; off; off >>= 1)
                m = fmaxf(m, __shfl_xor_sync(0xFFFFFFFFu, m, off, gsz));
            float s = (vx ? expf(o.x - m) : 0.0f) + (vy ? expf(o.y - m) : 0.0f)
                    + (vz ? expf(o.z - m) : 0.0f) + (vw ? expf(o.w - m) : 0.0f);
            for (int off = gsz >> 1; off; off >>= 1)
                s += __shfl_xor_sync(0xFFFFFFFFu, s, off, gsz);
            if (vd) {
                float lse = m + logf(s);
                float* orow = OUT + (size_t)d * M;
                if (vx) orow[f0 + 0] = o.x - lse;
                if (vy) orow[f0 + 1] = o.y - lse;
                if (vz) orow[f0 + 2] = o.z - lse;
                if (vw) orow[f0 + 3] = o.w - lse;
            }
        }
    }

    if (mode != 1) return;
    if (act) {
        atomicAdd(&sm_s[f0 + 0], ls.x); atomicAdd(&sm_q[f0 + 0], lq.x);
        atomicAdd(&sm_s[f0 + 1], ls.y); atomicAdd(&sm_q[f0 + 1], lq.y);
        atomicAdd(&sm_s[f0 + 2], ls.z); atomicAdd(&sm_q[f0 + 2], lq.z);
        atomicAdd(&sm_s[f0 + 3], ls.w); atomicAdd(&sm_q[f0 + 3], lq.w);
    }
    __syncthreads();
    for (int f = tid; f < M; f += blockDim.x) {
        atomicAdd(&g_sum[f], sm_s[f]);
        atomicAdd(&g_sumsq[f], sm_q[f]);
    }
    __threadfence();
    __syncthreads();
    __shared__ int is_last;
    if (tid == 0) {
        unsigned t = atomicAdd(&g_ticket, 1u);
        is_last = (t == gridDim.x - 1);
    }
    __syncthreads();
    if (is_last) {
        for (int f = tid; f < M; f += blockDim.x) {
            float mu = g_sum[f] / (float)N;
            float var = g_sumsq[f] / (float)N - mu * mu;
            float istd = rsqrtf(fmaxf(var, 0.0f) + 1e-5f);
            float sc = istd * gam[f];
            g_scale[f] = sc;
            g_shift[f] = bet[f] - mu * sc;
            g_sum[f] = 0.0f;
            g_sumsq[f] = 0.0f;
        }
        if (tid == 0) g_ticket = 0;
    }
}

// ---------------- orchestration ----------------
extern "C" void kernel_launch(void* const* d_in, const int* in_sizes, int n_in,
                              void* d_out, int out_size) {
    const float* x = (const float*)d_in[0];
    const void* ei = d_in[1];
    const float *W[5], *b[5], *gam[4], *bet[4];
    for (int i = 0; i < 5; i++) {
        W[i] = (const float*)d_in[2 + 2 * i];
        b[i] = (const float*)d_in[3 + 2 * i];
    }
    for (int i = 0; i < 4; i++) {
        gam[i] = (const float*)d_in[12 + 2 * i];
        bet[i] = (const float*)d_in[13 + 2 * i];
    }
    int dims[6];
    for (int i = 0; i < 5; i++) dims[i + 1] = in_sizes[3 + 2 * i];
    dims[0] = in_sizes[2] / dims[1];
    int N = in_sizes[0] / dims[0];
    int E = in_sizes[1] / 2;

    float *bufH, *bufG[2];
    cudaGetSymbolAddress((void**)&bufH, g_bufH);
    cudaGetSymbolAddress((void**)&bufG[0], g_bufG0);
    cudaGetSymbolAddress((void**)&bufG[1], g_bufG1);

    k_pre<<<PRE_BLOCKS, 256>>>(ei, N, E);

    const float* in = x;
    int Kp = dims[0];
    int transform = 0;
    for (int l = 0; l < 5; l++) {
        int K = dims[l], M = dims[l + 1];
        int Mp = (M + 3) & ~3;
        float* G = bufG[l & 1];

        int colT64 = (Mp + 63) / 64;
        int rows128 = (N + 127) / 128;
        if (rows128 * colT64 >= 148) {
            dim3 grid(colT64, rows128);
            k_gemm128<<<grid, 128>>>(in, W[l], bufH, N, K, M, Kp, Mp, transform);
        } else {
            dim3 grid(colT64, (N + 63) / 64);
            k_gemm64<<<grid, 256>>>(in, W[l], bufH, N, K, M, Kp, Mp, transform);
        }

        int nch4 = Mp >> 2;
        int ngroups, lg2;
        if (nch4 > 32)      { ngroups = (nch4 + 31) >> 5; lg2 = 5; }
        else if (nch4 > 16) { ngroups = 1; lg2 = 5; }
        else if (nch4 > 8)  { ngroups = 1; lg2 = 4; }
        else if (nch4 > 4)  { ngroups = 1; lg2 = 3; }
        else if (nch4 > 2)  { ngroups = 1; lg2 = 2; }
        else                { ngroups = 1; lg2 = 1; }
        int mode = (l < 4) ? 1 : 2;
        k_pull<<<1184, 256>>>(bufH, b[l], G, (float*)d_out, N, M, Mp, nch4,
                              ngroups, lg2, mode,
                              (l < 4) ? gam[l] : b[l], (l < 4) ? bet[l] : b[l]);

        if (l < 4) {
            in = G;
            Kp = Mp;
            transform = 1;
        }
    }
}

// round 14
// speedup vs baseline: 1.0852x; 1.0852x over previous
#include <cuda_runtime.h>
#include <math.h>

#define N_MAX 16384
#define F_MAX 256
#define E_MAX 524288
#define PRE_BLOCKS 148

// ---------------- scratch (device globals: no allocation allowed) ----------------
__device__ __align__(16) float g_bufH[N_MAX * F_MAX];   // Hs = h * dinv[row]
__device__ __align__(16) float g_bufG0[N_MAX * F_MAX];  // agg ping
__device__ __align__(16) float g_bufG1[N_MAX * F_MAX];  // agg pong
__device__ float g_dinv[N_MAX];
__device__ int   g_cin[N_MAX];
__device__ int   g_rowptr[N_MAX + 1];
__device__ int   g_fill[N_MAX];
__device__ int   g_csr[E_MAX];
__device__ float g_sum[F_MAX], g_sumsq[F_MAX];
__device__ float g_scale[F_MAX], g_shift[F_MAX];
__device__ unsigned g_ticket;
__device__ unsigned g_bar;   // zero-init; reset by GEMM launches

// ---------------- fused preamble ----------------
__device__ __forceinline__ void gbar(unsigned target) {
    __syncthreads();
    if (threadIdx.x == 0) {
        __threadfence();
        atomicAdd(&g_bar, 1u);
        while (*(volatile unsigned*)&g_bar < target) __nanosleep(64);
        __threadfence();
    }
    __syncthreads();
}

__device__ __forceinline__ void edge_sd_z(const void* ei, int z, int e, int E,
                                          int& s, int& d) {
    if (z) {
        const long long* p = (const long long*)ei;
        s = (int)p[e];
        d = (int)p[(long long)E + e];
    } else {
        const int* p = (const int*)ei;
        s = p[e];
        d = p[E + e];
    }
}

__global__ void k_pre(const void* __restrict__ ei, int N, int E) {
    const int* eip = (const int*)ei;
    int z = 1;
#pragma unroll
    for (int t = 0; t < 32; t++) z &= (eip[2 * t + 1] == 0);

    int tid = threadIdx.x;
    int gt = blockIdx.x * blockDim.x + tid;
    int nthr = gridDim.x * blockDim.x;

    for (int i = gt; i < N; i += nthr) { g_cin[i] = 0; g_fill[i] = 0; }
    if (gt < F_MAX) { g_sum[gt] = 0.0f; g_sumsq[gt] = 0.0f; }
    if (gt == 0) g_ticket = 0;
    gbar(1 * PRE_BLOCKS);

    for (int e = gt; e < E; e += nthr) {
        int s, d;
        edge_sd_z(ei, z, e, E, s, d);
        atomicAdd(&g_cin[d], 1);
    }
    gbar(2 * PRE_BLOCKS);

    if (blockIdx.x == 0) {
        __shared__ int wsum[8];
        int chunk = (N + 255) >> 8;
        int t0 = tid * chunk, t1 = min(N, t0 + chunk);
        int s = 0;
        for (int i = t0; i < t1; i++) {
            int c = g_cin[i];
            g_dinv[i] = rsqrtf((float)c + 1.0f);
            s += c;
        }
        int lane = tid & 31, wid = tid >> 5;
        int v = s;
#pragma unroll
        for (int o = 1; o < 32; o <<= 1) {
            int u = __shfl_up_sync(0xFFFFFFFFu, v, o);
            if (lane >= o) v += u;
        }
        if (lane == 31) wsum[wid] = v;
        __syncthreads();
        if (wid == 0 && lane < 8) {
            int w = wsum[lane];
#pragma unroll
            for (int o = 1; o < 8; o <<= 1) {
                int u = __shfl_up_sync(0xFFu, w, o);
                if (lane >= o) w += u;
            }
            wsum[lane] = w;
        }
        __syncthreads();
        int run = v - s + (wid > 0 ? wsum[wid - 1] : 0);
        for (int i = t0; i < t1; i++) {
            g_rowptr[i] = run;
            run += g_cin[i];
        }
        if (t0 < N && t1 == N) g_rowptr[N] = run;
    }
    gbar(3 * PRE_BLOCKS);

    for (int e = gt; e < E; e += nthr) {
        int s, d;
        edge_sd_z(ei, z, e, E, s, d);
        int pos = g_rowptr[d] + atomicAdd(&g_fill[d], 1);
        g_csr[pos] = s;
    }
}

// ---------------- GEMM 128x64 tile (8x4 micro), DOUBLE-BUFFERED (R12 winner) ---
__global__ __launch_bounds__(256) void k_gemm128(
        const float* __restrict__ A, const float* __restrict__ B,
        float* __restrict__ Hs,
        int N, int K, int M, int Kp, int Mp, int transform) {
    if (threadIdx.x == 0 && blockIdx.x == 0 && blockIdx.y == 0) g_bar = 0;
    __shared__ __align__(16) float As[2][16][132];
    __shared__ __align__(16) float Bs[2][16][68];
    int tid = threadIdx.x;
    int tx = tid & 15, ty = tid >> 4;
    int row0 = blockIdx.y * 128, col0 = blockIdx.x * 64;
    float acc[8][4] = {};

    int T = (K + 15) >> 4;

    int ar = tid >> 1;
    int c8 = (tid & 1) * 8;
    int agr = row0 + ar;
    int br = tid >> 4;
    int bc = (tid & 15) * 4;

    float4 pa0, pa1;
    float pb[4];

#define PREFETCH(t)                                                              \
    {                                                                            \
        int k0 = (t) << 4;                                                       \
        pa0 = make_float4(0, 0, 0, 0);                                           \
        pa1 = make_float4(0, 0, 0, 0);                                           \
        if (agr < N) {                                                           \
            pa0 = *(const float4*)(A + (size_t)agr * Kp + k0 + c8);              \
            pa1 = *(const float4*)(A + (size_t)agr * Kp + k0 + c8 + 4);          \
            if (transform) {                                                     \
                pa0.x = fmaf(fmaxf(pa0.x, 0.0f), g_scale[k0 + c8 + 0], g_shift[k0 + c8 + 0]); \
                pa0.y = fmaf(fmaxf(pa0.y, 0.0f), g_scale[k0 + c8 + 1], g_shift[k0 + c8 + 1]); \
                pa0.z = fmaf(fmaxf(pa0.z, 0.0f), g_scale[k0 + c8 + 2], g_shift[k0 + c8 + 2]); \
                pa0.w = fmaf(fmaxf(pa0.w, 0.0f), g_scale[k0 + c8 + 3], g_shift[k0 + c8 + 3]); \
                pa1.x = fmaf(fmaxf(pa1.x, 0.0f), g_scale[k0 + c8 + 4], g_shift[k0 + c8 + 4]); \
                pa1.y = fmaf(fmaxf(pa1.y, 0.0f), g_scale[k0 + c8 + 5], g_shift[k0 + c8 + 5]); \
                pa1.z = fmaf(fmaxf(pa1.z, 0.0f), g_scale[k0 + c8 + 6], g_shift[k0 + c8 + 6]); \
                pa1.w = fmaf(fmaxf(pa1.w, 0.0f), g_scale[k0 + c8 + 7], g_shift[k0 + c8 + 7]); \
            }                                                                    \
        }                                                                        \
        int gk = k0 + br;                                                        \
        _Pragma("unroll")                                                        \
        for (int i = 0; i < 4; i++) {                                            \
            int gc = col0 + bc + i;                                              \
            pb[i] = (gk < K && gc < M) ? B[(size_t)gk * M + gc] : 0.0f;          \
        }                                                                        \
    }

#define STORE(buf)                                                               \
    {                                                                            \
        As[buf][c8 + 0][ar] = pa0.x;                                             \
        As[buf][c8 + 1][ar] = pa0.y;                                             \
        As[buf][c8 + 2][ar] = pa0.z;                                             \
        As[buf][c8 + 3][ar] = pa0.w;                                             \
        As[buf][c8 + 4][ar] = pa1.x;                                             \
        As[buf][c8 + 5][ar] = pa1.y;                                             \
        As[buf][c8 + 6][ar] = pa1.z;                                             \
        As[buf][c8 + 7][ar] = pa1.w;                                             \
        *(float4*)&Bs[buf][br][bc] = make_float4(pb[0], pb[1], pb[2], pb[3]);    \
    }

    PREFETCH(0)
    STORE(0)
    __syncthreads();

    for (int t = 0; t < T; t++) {
        int cur = t & 1;
        bool havenext = (t + 1 < T);
        if (havenext) PREFETCH(t + 1)
#pragma unroll
        for (int kk = 0; kk < 16; kk++) {
            float4 a0 = *(const float4*)&As[cur][kk][ty * 8];
            float4 a1 = *(const float4*)&As[cur][kk][ty * 8 + 4];
            float4 b4 = *(const float4*)&Bs[cur][kk][tx * 4];
            float a[8] = {a0.x, a0.y, a0.z, a0.w, a1.x, a1.y, a1.z, a1.w};
            float bb[4] = {b4.x, b4.y, b4.z, b4.w};
#pragma unroll
            for (int i = 0; i < 8; i++)
#pragma unroll
                for (int j = 0; j < 4; j++)
                    acc[i][j] = fmaf(a[i], bb[j], acc[i][j]);
        }
        if (havenext) {
            STORE(cur ^ 1)
            __syncthreads();
        }
    }
#pragma unroll
    for (int i = 0; i < 8; i++) {
        int gr = row0 + ty * 8 + i;
        if (gr >= N) continue;
        float dd = g_dinv[gr];
#pragma unroll
        for (int j = 0; j < 4; j++) {
            int gc = col0 + tx * 4 + j;
            if (gc < Mp)
                Hs[(size_t)gr * Mp + gc] = (gc < M) ? acc[i][j] * dd : 0.0f;
        }
    }
#undef PREFETCH
#undef STORE
}

// ---------------- GEMM 64x64 tile (4x4 micro), DOUBLE-BUFFERED -----------------
__global__ __launch_bounds__(256) void k_gemm64(
        const float* __restrict__ A, const float* __restrict__ B,
        float* __restrict__ Hs,
        int N, int K, int M, int Kp, int Mp, int transform) {
    if (threadIdx.x == 0 && blockIdx.x == 0 && blockIdx.y == 0) g_bar = 0;
    __shared__ __align__(16) float As[2][16][68];
    __shared__ __align__(16) float Bs[2][16][68];
    int tid = threadIdx.x;
    int tx = tid & 15, ty = tid >> 4;
    int row0 = blockIdx.y * 64, col0 = blockIdx.x * 64;
    float acc[4][4] = {};

    int T = (K + 15) >> 4;

    // A: 64 rows x 16 k = 256 float4; thread -> row ar, k-cols kc..kc+3
    int ar = tid >> 2;
    int kc = (tid & 3) * 4;
    int agr = row0 + ar;
    // B: 16 x 64 = 256 float4; thread -> row br, cols bc..bc+3
    int br = tid >> 4;
    int bc = (tid & 15) * 4;

    float4 pa;
    float pb[4];

#define PREFETCH(t)                                                              \
    {                                                                            \
        int k0 = (t) << 4;                                                       \
        pa = make_float4(0, 0, 0, 0);                                            \
        if (agr < N) {                                                           \
            pa = *(const float4*)(A + (size_t)agr * Kp + k0 + kc);               \
            if (transform) {                                                     \
                pa.x = fmaf(fmaxf(pa.x, 0.0f), g_scale[k0 + kc + 0], g_shift[k0 + kc + 0]); \
                pa.y = fmaf(fmaxf(pa.y, 0.0f), g_scale[k0 + kc + 1], g_shift[k0 + kc + 1]); \
                pa.z = fmaf(fmaxf(pa.z, 0.0f), g_scale[k0 + kc + 2], g_shift[k0 + kc + 2]); \
                pa.w = fmaf(fmaxf(pa.w, 0.0f), g_scale[k0 + kc + 3], g_shift[k0 + kc + 3]); \
            }                                                                    \
        }                                                                        \
        int gk = k0 + br;                                                        \
        _Pragma("unroll")                                                        \
        for (int i = 0; i < 4; i++) {                                            \
            int gc = col0 + bc + i;                                              \
            pb[i] = (gk < K && gc < M) ? B[(size_t)gk * M + gc] : 0.0f;          \
        }                                                                        \
    }

#define STORE(buf)                                                               \
    {                                                                            \
        As[buf][kc + 0][ar] = pa.x;                                              \
        As[buf][kc + 1][ar] = pa.y;                                              \
        As[buf][kc + 2][ar] = pa.z;                                              \
        As[buf][kc + 3][ar] = pa.w;                                              \
        *(float4*)&Bs[buf][br][bc] = make_float4(pb[0], pb[1], pb[2], pb[3]);    \
    }

    PREFETCH(0)
    STORE(0)
    __syncthreads();

    for (int t = 0; t < T; t++) {
        int cur = t & 1;
        bool havenext = (t + 1 < T);
        if (havenext) PREFETCH(t + 1)
#pragma unroll
        for (int kk = 0; kk < 16; kk++) {
            float4 a4 = *(const float4*)&As[cur][kk][ty * 4];
            float4 b4 = *(const float4*)&Bs[cur][kk][tx * 4];
            float a[4] = {a4.x, a4.y, a4.z, a4.w};
            float bb[4] = {b4.x, b4.y, b4.z, b4.w};
#pragma unroll
            for (int i = 0; i < 4; i++)
#pragma unroll
                for (int j = 0; j < 4; j++)
                    acc[i][j] = fmaf(a[i], bb[j], acc[i][j]);
        }
        if (havenext) {
            STORE(cur ^ 1)
            __syncthreads();
        }
    }
#pragma unroll
    for (int i = 0; i < 4; i++) {
        int gr = row0 + ty * 4 + i;
        if (gr >= N) continue;
        float dd = g_dinv[gr];
#pragma unroll
        for (int j = 0; j < 4; j++) {
            int gc = col0 + tx * 4 + j;
            if (gc < Mp)
                Hs[(size_t)gr * Mp + gc] = (gc < M) ? acc[i][j] * dd : 0.0f;
        }
    }
#undef PREFETCH
#undef STORE
}

// ---------------- coalesced CSR pull, sub-warp packed --------------------------
__global__ void k_pull(const float* __restrict__ Hs, const float* __restrict__ bias,
                       float* __restrict__ G, float* __restrict__ OUT,
                       int N, int M, int Mp, int nch4, int ngroups, int lg2gsz,
                       int mode,
                       const float* __restrict__ gam, const float* __restrict__ bet) {
    __shared__ float sm_s[F_MAX], sm_q[F_MAX];
    int tid = threadIdx.x;
    if (mode == 1) {
        for (int f = tid; f < F_MAX; f += blockDim.x) { sm_s[f] = 0.0f; sm_q[f] = 0.0f; }
        __syncthreads();
    }
    int gsz = 1 << lg2gsz;
    int epw = 32 >> lg2gsz;
    int lane = tid & 31;
    int sub = lane >> lg2gsz;
    int gw = (blockIdx.x * blockDim.x + tid) >> 5;
    int nw = (gridDim.x * blockDim.x) >> 5;
    int grp = (ngroups > 1) ? (gw % ngroups) : 0;
    int c = (lane & (gsz - 1)) + (grp << 5);
    bool act = c < nch4;
    int f0 = c << 2;
    float4 b4 = make_float4(0, 0, 0, 0);
    if (act) {
        b4.x = (f0 + 0 < M) ? bias[f0 + 0] : 0.0f;
        b4.y = (f0 + 1 < M) ? bias[f0 + 1] : 0.0f;
        b4.z = (f0 + 2 < M) ? bias[f0 + 2] : 0.0f;
        b4.w = (f0 + 3 < M) ? bias[f0 + 3] : 0.0f;
    }
    int wbase = gw / ngroups;
    int wstride = nw / ngroups;
    float4 ls = make_float4(0, 0, 0, 0), lq = make_float4(0, 0, 0, 0);

    for (int w = wbase; w * epw < N; w += wstride) {
        int d = w * epw + sub;
        bool vd = (d < N) && act;
        int beg = 0, end = 0;
        float dd = 0.0f;
        float4 acc = make_float4(0, 0, 0, 0);
        if (vd) {
            beg = g_rowptr[d];
            end = g_rowptr[d + 1];
            dd = g_dinv[d];
            acc = ((const float4*)(Hs + (size_t)d * Mp))[c];
        }
        int e = beg;
        for (; e + 7 < end; e += 8) {
            int s0 = g_csr[e], s1 = g_csr[e + 1], s2 = g_csr[e + 2], s3 = g_csr[e + 3];
            int s4 = g_csr[e + 4], s5 = g_csr[e + 5], s6 = g_csr[e + 6], s7 = g_csr[e + 7];
            float4 v0 = ((const float4*)(Hs + (size_t)s0 * Mp))[c];
            float4 v1 = ((const float4*)(Hs + (size_t)s1 * Mp))[c];
            float4 v2 = ((const float4*)(Hs + (size_t)s2 * Mp))[c];
            float4 v3 = ((const float4*)(Hs + (size_t)s3 * Mp))[c];
            float4 v4 = ((const float4*)(Hs + (size_t)s4 * Mp))[c];
            float4 v5 = ((const float4*)(Hs + (size_t)s5 * Mp))[c];
            float4 v6 = ((const float4*)(Hs + (size_t)s6 * Mp))[c];
            float4 v7 = ((const float4*)(Hs + (size_t)s7 * Mp))[c];
            acc.x += ((v0.x + v1.x) + (v2.x + v3.x)) + ((v4.x + v5.x) + (v6.x + v7.x));
            acc.y += ((v0.y + v1.y) + (v2.y + v3.y)) + ((v4.y + v5.y) + (v6.y + v7.y));
            acc.z += ((v0.z + v1.z) + (v2.z + v3.z)) + ((v4.z + v5.z) + (v6.z + v7.z));
            acc.w += ((v0.w + v1.w) + (v2.w + v3.w)) + ((v4.w + v5.w) + (v6.w + v7.w));
        }
        for (; e + 1 < end; e += 2) {
            int s0 = g_csr[e], s1 = g_csr[e + 1];
            float4 v0 = ((const float4*)(Hs + (size_t)s0 * Mp))[c];
            float4 v1 = ((const float4*)(Hs + (size_t)s1 * Mp))[c];
            acc.x += v0.x + v1.x; acc.y += v0.y + v1.y;
            acc.z += v0.z + v1.z; acc.w += v0.w + v1.w;
        }
        if (e < end) {
            int s0 = g_csr[e];
            float4 v0 = ((const float4*)(Hs + (size_t)s0 * Mp))[c];
            acc.x += v0.x; acc.y += v0.y; acc.z += v0.z; acc.w += v0.w;
        }
        float4 o;
        o.x = fmaf(dd, acc.x, b4.x);
        o.y = fmaf(dd, acc.y, b4.y);
        o.z = fmaf(dd, acc.z, b4.z);
        o.w = fmaf(dd, acc.w, b4.w);

        if (mode == 1) {
            if (vd) {
                ((float4*)(G + (size_t)d * Mp))[c] = o;
                float rx = fmaxf(o.x, 0.0f), ry = fmaxf(o.y, 0.0f);
                float rz = fmaxf(o.z, 0.0f), rw = fmaxf(o.w, 0.0f);
                ls.x += rx; ls.y += ry; ls.z += rz; ls.w += rw;
                lq.x += rx * rx; lq.y += ry * ry; lq.z += rz * rz; lq.w += rw * rw;
            }
        } else {
            bool vx = vd && (f0 + 0 < M), vy = vd && (f0 + 1 < M);
            bool vz = vd && (f0 + 2 < M), vw = vd && (f0 + 3 < M);
            float m = fmaxf(fmaxf(vx ? o.x : -1e30f, vy ? o.y : -1e30f),
                            fmaxf(vz ? o.z : -1e30f, vw ? o.w : -1e30f));
            for (int off = gsz >> 1; off; off >>= 1)
                m = fmaxf(m, __shfl_xor_sync(0xFFFFFFFFu, m, off, gsz));
            float s = (vx ? expf(o.x - m) : 0.0f) + (vy ? expf(o.y - m) : 0.0f)
                    + (vz ? expf(o.z - m) : 0.0f) + (vw ? expf(o.w - m) : 0.0f);
            for (int off = gsz >> 1; off; off >>= 1)
                s += __shfl_xor_sync(0xFFFFFFFFu, s, off, gsz);
            if (vd) {
                float lse = m + logf(s);
                float* orow = OUT + (size_t)d * M;
                if (vx) orow[f0 + 0] = o.x - lse;
                if (vy) orow[f0 + 1] = o.y - lse;
                if (vz) orow[f0 + 2] = o.z - lse;
                if (vw) orow[f0 + 3] = o.w - lse;
            }
        }
    }

    if (mode != 1) return;
    if (act) {
        atomicAdd(&sm_s[f0 + 0], ls.x); atomicAdd(&sm_q[f0 + 0], lq.x);
        atomicAdd(&sm_s[f0 + 1], ls.y); atomicAdd(&sm_q[f0 + 1], lq.y);
        atomicAdd(&sm_s[f0 + 2], ls.z); atomicAdd(&sm_q[f0 + 2], lq.z);
        atomicAdd(&sm_s[f0 + 3], ls.w); atomicAdd(&sm_q[f0 + 3], lq.w);
    }
    __syncthreads();
    for (int f = tid; f < M; f += blockDim.x) {
        atomicAdd(&g_sum[f], sm_s[f]);
        atomicAdd(&g_sumsq[f], sm_q[f]);
    }
    __threadfence();
    __syncthreads();
    __shared__ int is_last;
    if (tid == 0) {
        unsigned t = atomicAdd(&g_ticket, 1u);
        is_last = (t == gridDim.x - 1);
    }
    __syncthreads();
    if (is_last) {
        for (int f = tid; f < M; f += blockDim.x) {
            float mu = g_sum[f] / (float)N;
            float var = g_sumsq[f] / (float)N - mu * mu;
            float istd = rsqrtf(fmaxf(var, 0.0f) + 1e-5f);
            float sc = istd * gam[f];
            g_scale[f] = sc;
            g_shift[f] = bet[f] - mu * sc;
            g_sum[f] = 0.0f;
            g_sumsq[f] = 0.0f;
        }
        if (tid == 0) g_ticket = 0;
    }
}

// ---------------- orchestration ----------------
extern "C" void kernel_launch(void* const* d_in, const int* in_sizes, int n_in,
                              void* d_out, int out_size) {
    const float* x = (const float*)d_in[0];
    const void* ei = d_in[1];
    const float *W[5], *b[5], *gam[4], *bet[4];
    for (int i = 0; i < 5; i++) {
        W[i] = (const float*)d_in[2 + 2 * i];
        b[i] = (const float*)d_in[3 + 2 * i];
    }
    for (int i = 0; i < 4; i++) {
        gam[i] = (const float*)d_in[12 + 2 * i];
        bet[i] = (const float*)d_in[13 + 2 * i];
    }
    int dims[6];
    for (int i = 0; i < 5; i++) dims[i + 1] = in_sizes[3 + 2 * i];
    dims[0] = in_sizes[2] / dims[1];
    int N = in_sizes[0] / dims[0];
    int E = in_sizes[1] / 2;

    float *bufH, *bufG[2];
    cudaGetSymbolAddress((void**)&bufH, g_bufH);
    cudaGetSymbolAddress((void**)&bufG[0], g_bufG0);
    cudaGetSymbolAddress((void**)&bufG[1], g_bufG1);

    k_pre<<<PRE_BLOCKS, 256>>>(ei, N, E);

    const float* in = x;
    int Kp = dims[0];
    int transform = 0;
    for (int l = 0; l < 5; l++) {
        int K = dims[l], M = dims[l + 1];
        int Mp = (M + 3) & ~3;
        float* G = bufG[l & 1];

        int colT64 = (Mp + 63) / 64;
        int rows128 = (N + 127) / 128;
        if (rows128 * colT64 >= 148) {
            dim3 grid(colT64, rows128);
            k_gemm128<<<grid, 256>>>(in, W[l], bufH, N, K, M, Kp, Mp, transform);
        } else {
            dim3 grid(colT64, (N + 63) / 64);
            k_gemm64<<<grid, 256>>>(in, W[l], bufH, N, K, M, Kp, Mp, transform);
        }

        int nch4 = Mp >> 2;
        int ngroups, lg2;
        if (nch4 > 32)      { ngroups = (nch4 + 31) >> 5; lg2 = 5; }
        else if (nch4 > 16) { ngroups = 1; lg2 = 5; }
        else if (nch4 > 8)  { ngroups = 1; lg2 = 4; }
        else if (nch4 > 4)  { ngroups = 1; lg2 = 3; }
        else if (nch4 > 2)  { ngroups = 1; lg2 = 2; }
        else                { ngroups = 1; lg2 = 1; }
        int mode = (l < 4) ? 1 : 2;
        k_pull<<<1184, 256>>>(bufH, b[l], G, (float*)d_out, N, M, Mp, nch4,
                              ngroups, lg2, mode,
                              (l < 4) ? gam[l] : b[l], (l < 4) ? bet[l] : b[l]);

        if (l < 4) {
            in = G;
            Kp = Mp;
            transform = 1;
        }
    }
}

// round 15
// speedup vs baseline: 1.1503x; 1.0600x over previous
#include <cuda_runtime.h>
#include <math.h>

#define N_MAX 16384
#define F_MAX 256
#define E_MAX 524288
#define PRE_BLOCKS 148

// ---------------- scratch (device globals: no allocation allowed) ----------------
__device__ __align__(16) float g_bufH[N_MAX * F_MAX];   // Hs = h * dinv[row]
__device__ __align__(16) float g_bufG0[N_MAX * F_MAX];  // agg ping
__device__ __align__(16) float g_bufG1[N_MAX * F_MAX];  // agg pong
__device__ float g_dinv[N_MAX];
__device__ int   g_cin[N_MAX];
__device__ int   g_rowptr[N_MAX + 1];
__device__ int   g_fill[N_MAX];
__device__ int   g_csr[E_MAX];
__device__ float g_sum[F_MAX], g_sumsq[F_MAX];
__device__ float g_scale[F_MAX], g_shift[F_MAX];
__device__ unsigned g_ticket;
__device__ unsigned g_bar;   // zero-init; reset by GEMM launches

// ---------------- fused preamble ----------------
__device__ __forceinline__ void gbar(unsigned target) {
    __syncthreads();
    if (threadIdx.x == 0) {
        __threadfence();
        atomicAdd(&g_bar, 1u);
        while (*(volatile unsigned*)&g_bar < target) __nanosleep(64);
        __threadfence();
    }
    __syncthreads();
}

__device__ __forceinline__ void edge_sd_z(const void* ei, int z, int e, int E,
                                          int& s, int& d) {
    if (z) {
        const long long* p = (const long long*)ei;
        s = (int)p[e];
        d = (int)p[(long long)E + e];
    } else {
        const int* p = (const int*)ei;
        s = p[e];
        d = p[E + e];
    }
}

__global__ void k_pre(const void* __restrict__ ei, int N, int E) {
    const int* eip = (const int*)ei;
    int z = 1;
#pragma unroll
    for (int t = 0; t < 32; t++) z &= (eip[2 * t + 1] == 0);

    int tid = threadIdx.x;
    int gt = blockIdx.x * blockDim.x + tid;
    int nthr = gridDim.x * blockDim.x;

    for (int i = gt; i < N; i += nthr) { g_cin[i] = 0; g_fill[i] = 0; }
    if (gt < F_MAX) { g_sum[gt] = 0.0f; g_sumsq[gt] = 0.0f; }
    if (gt == 0) g_ticket = 0;
    gbar(1 * PRE_BLOCKS);

    for (int e = gt; e < E; e += nthr) {
        int s, d;
        edge_sd_z(ei, z, e, E, s, d);
        atomicAdd(&g_cin[d], 1);
    }
    gbar(2 * PRE_BLOCKS);

    if (blockIdx.x == 0) {
        __shared__ int wsum[8];
        int chunk = (N + 255) >> 8;
        int t0 = tid * chunk, t1 = min(N, t0 + chunk);
        int s = 0;
        for (int i = t0; i < t1; i++) {
            int c = g_cin[i];
            g_dinv[i] = rsqrtf((float)c + 1.0f);
            s += c;
        }
        int lane = tid & 31, wid = tid >> 5;
        int v = s;
#pragma unroll
        for (int o = 1; o < 32; o <<= 1) {
            int u = __shfl_up_sync(0xFFFFFFFFu, v, o);
            if (lane >= o) v += u;
        }
        if (lane == 31) wsum[wid] = v;
        __syncthreads();
        if (wid == 0 && lane < 8) {
            int w = wsum[lane];
#pragma unroll
            for (int o = 1; o < 8; o <<= 1) {
                int u = __shfl_up_sync(0xFFu, w, o);
                if (lane >= o) w += u;
            }
            wsum[lane] = w;
        }
        __syncthreads();
        int run = v - s + (wid > 0 ? wsum[wid - 1] : 0);
        for (int i = t0; i < t1; i++) {
            g_rowptr[i] = run;
            run += g_cin[i];
        }
        if (t0 < N && t1 == N) g_rowptr[N] = run;
    }
    gbar(3 * PRE_BLOCKS);

    for (int e = gt; e < E; e += nthr) {
        int s, d;
        edge_sd_z(ei, z, e, E, s, d);
        int pos = g_rowptr[d] + atomicAdd(&g_fill[d], 1);
        g_csr[pos] = s;
    }
}

// ---------------- GEMM 128x64 tile (8x4 micro), double-buffered, FFMA2 ---------
// Accumulators packed as f32x2 along rows: acc2[p][j] = (acc[2p][j], acc[2p+1][j]).
// A pairs come free as double2 LDS from [k][row] layout; B dup'd via mov.b64.
__global__ __launch_bounds__(256) void k_gemm128(
        const float* __restrict__ A, const float* __restrict__ B,
        float* __restrict__ Hs,
        int N, int K, int M, int Kp, int Mp, int transform) {
    if (threadIdx.x == 0 && blockIdx.x == 0 && blockIdx.y == 0) g_bar = 0;
    __shared__ __align__(16) float As[2][16][132];
    __shared__ __align__(16) float Bs[2][16][68];
    int tid = threadIdx.x;
    int tx = tid & 15, ty = tid >> 4;
    int row0 = blockIdx.y * 128, col0 = blockIdx.x * 64;
    unsigned long long acc2[4][4] = {};   // (row 2p, row 2p+1) x col j

    int T = (K + 15) >> 4;

    int ar = tid >> 1;
    int c8 = (tid & 1) * 8;
    int agr = row0 + ar;
    int br = tid >> 4;
    int bc = (tid & 15) * 4;

    float4 pa0, pa1;
    float pb[4];

#define PREFETCH(t)                                                              \
    {                                                                            \
        int k0 = (t) << 4;                                                       \
        pa0 = make_float4(0, 0, 0, 0);                                           \
        pa1 = make_float4(0, 0, 0, 0);                                           \
        if (agr < N) {                                                           \
            pa0 = *(const float4*)(A + (size_t)agr * Kp + k0 + c8);              \
            pa1 = *(const float4*)(A + (size_t)agr * Kp + k0 + c8 + 4);          \
            if (transform) {                                                     \
                pa0.x = fmaf(fmaxf(pa0.x, 0.0f), g_scale[k0 + c8 + 0], g_shift[k0 + c8 + 0]); \
                pa0.y = fmaf(fmaxf(pa0.y, 0.0f), g_scale[k0 + c8 + 1], g_shift[k0 + c8 + 1]); \
                pa0.z = fmaf(fmaxf(pa0.z, 0.0f), g_scale[k0 + c8 + 2], g_shift[k0 + c8 + 2]); \
                pa0.w = fmaf(fmaxf(pa0.w, 0.0f), g_scale[k0 + c8 + 3], g_shift[k0 + c8 + 3]); \
                pa1.x = fmaf(fmaxf(pa1.x, 0.0f), g_scale[k0 + c8 + 4], g_shift[k0 + c8 + 4]); \
                pa1.y = fmaf(fmaxf(pa1.y, 0.0f), g_scale[k0 + c8 + 5], g_shift[k0 + c8 + 5]); \
                pa1.z = fmaf(fmaxf(pa1.z, 0.0f), g_scale[k0 + c8 + 6], g_shift[k0 + c8 + 6]); \
                pa1.w = fmaf(fmaxf(pa1.w, 0.0f), g_scale[k0 + c8 + 7], g_shift[k0 + c8 + 7]); \
            }                                                                    \
        }                                                                        \
        int gk = k0 + br;                                                        \
        _Pragma("unroll")                                                        \
        for (int i = 0; i < 4; i++) {                                            \
            int gc = col0 + bc + i;                                              \
            pb[i] = (gk < K && gc < M) ? B[(size_t)gk * M + gc] : 0.0f;          \
        }                                                                        \
    }

#define STORE(buf)                                                               \
    {                                                                            \
        As[buf][c8 + 0][ar] = pa0.x;                                             \
        As[buf][c8 + 1][ar] = pa0.y;                                             \
        As[buf][c8 + 2][ar] = pa0.z;                                             \
        As[buf][c8 + 3][ar] = pa0.w;                                             \
        As[buf][c8 + 4][ar] = pa1.x;                                             \
        As[buf][c8 + 5][ar] = pa1.y;                                             \
        As[buf][c8 + 6][ar] = pa1.z;                                             \
        As[buf][c8 + 7][ar] = pa1.w;                                             \
        *(float4*)&Bs[buf][br][bc] = make_float4(pb[0], pb[1], pb[2], pb[3]);    \
    }

    PREFETCH(0)
    STORE(0)
    __syncthreads();

    for (int t = 0; t < T; t++) {
        int cur = t & 1;
        bool havenext = (t + 1 < T);
        if (havenext) PREFETCH(t + 1)
#pragma unroll
        for (int kk = 0; kk < 16; kk++) {
            // A row-pairs: (a0,a1),(a2,a3),(a4,a5),(a6,a7) as packed f32x2
            double2 a01 = *(const double2*)&As[cur][kk][ty * 8];
            double2 a23 = *(const double2*)&As[cur][kk][ty * 8 + 4];
            unsigned long long ap[4];
            ap[0] = __double_as_longlong(a01.x);
            ap[1] = __double_as_longlong(a01.y);
            ap[2] = __double_as_longlong(a23.x);
            ap[3] = __double_as_longlong(a23.y);
            float4 b4 = *(const float4*)&Bs[cur][kk][tx * 4];
            unsigned long long bd[4];
            asm("mov.b64 %0, {%1,%1};" : "=l"(bd[0]) : "f"(b4.x));
            asm("mov.b64 %0, {%1,%1};" : "=l"(bd[1]) : "f"(b4.y));
            asm("mov.b64 %0, {%1,%1};" : "=l"(bd[2]) : "f"(b4.z));
            asm("mov.b64 %0, {%1,%1};" : "=l"(bd[3]) : "f"(b4.w));
#pragma unroll
            for (int p = 0; p < 4; p++)
#pragma unroll
                for (int j = 0; j < 4; j++)
                    asm("fma.rn.f32x2 %0, %1, %2, %0;"
                        : "+l"(acc2[p][j]) : "l"(ap[p]), "l"(bd[j]));
        }
        if (havenext) {
            STORE(cur ^ 1)
            __syncthreads();
        }
    }
    // epilogue: unpack row pairs
#pragma unroll
    for (int p = 0; p < 4; p++) {
        int gr0 = row0 + ty * 8 + 2 * p;
        int gr1 = gr0 + 1;
#pragma unroll
        for (int j = 0; j < 4; j++) {
            float lo, hi;
            asm("mov.b64 {%0,%1}, %2;" : "=f"(lo), "=f"(hi) : "l"(acc2[p][j]));
            int gc = col0 + tx * 4 + j;
            if (gc < Mp) {
                if (gr0 < N) {
                    float dd = g_dinv[gr0];
                    Hs[(size_t)gr0 * Mp + gc] = (gc < M) ? lo * dd : 0.0f;
                }
                if (gr1 < N) {
                    float dd = g_dinv[gr1];
                    Hs[(size_t)gr1 * Mp + gc] = (gc < M) ? hi * dd : 0.0f;
                }
            }
        }
    }
#undef PREFETCH
#undef STORE
}

// ---------------- GEMM 64x64 tile (4x4 micro), DOUBLE-BUFFERED -----------------
__global__ __launch_bounds__(256) void k_gemm64(
        const float* __restrict__ A, const float* __restrict__ B,
        float* __restrict__ Hs,
        int N, int K, int M, int Kp, int Mp, int transform) {
    if (threadIdx.x == 0 && blockIdx.x == 0 && blockIdx.y == 0) g_bar = 0;
    __shared__ __align__(16) float As[2][16][68];
    __shared__ __align__(16) float Bs[2][16][68];
    int tid = threadIdx.x;
    int tx = tid & 15, ty = tid >> 4;
    int row0 = blockIdx.y * 64, col0 = blockIdx.x * 64;
    float acc[4][4] = {};

    int T = (K + 15) >> 4;

    int ar = tid >> 2;
    int kc = (tid & 3) * 4;
    int agr = row0 + ar;
    int br = tid >> 4;
    int bc = (tid & 15) * 4;

    float4 pa;
    float pb[4];

#define PREFETCH(t)                                                              \
    {                                                                            \
        int k0 = (t) << 4;                                                       \
        pa = make_float4(0, 0, 0, 0);                                            \
        if (agr < N) {                                                           \
            pa = *(const float4*)(A + (size_t)agr * Kp + k0 + kc);               \
            if (transform) {                                                     \
                pa.x = fmaf(fmaxf(pa.x, 0.0f), g_scale[k0 + kc + 0], g_shift[k0 + kc + 0]); \
                pa.y = fmaf(fmaxf(pa.y, 0.0f), g_scale[k0 + kc + 1], g_shift[k0 + kc + 1]); \
                pa.z = fmaf(fmaxf(pa.z, 0.0f), g_scale[k0 + kc + 2], g_shift[k0 + kc + 2]); \
                pa.w = fmaf(fmaxf(pa.w, 0.0f), g_scale[k0 + kc + 3], g_shift[k0 + kc + 3]); \
            }                                                                    \
        }                                                                        \
        int gk = k0 + br;                                                        \
        _Pragma("unroll")                                                        \
        for (int i = 0; i < 4; i++) {                                            \
            int gc = col0 + bc + i;                                              \
            pb[i] = (gk < K && gc < M) ? B[(size_t)gk * M + gc] : 0.0f;          \
        }                                                                        \
    }

#define STORE(buf)                                                               \
    {                                                                            \
        As[buf][kc + 0][ar] = pa.x;                                              \
        As[buf][kc + 1][ar] = pa.y;                                              \
        As[buf][kc + 2][ar] = pa.z;                                              \
        As[buf][kc + 3][ar] = pa.w;                                              \
        *(float4*)&Bs[buf][br][bc] = make_float4(pb[0], pb[1], pb[2], pb[3]);    \
    }

    PREFETCH(0)
    STORE(0)
    __syncthreads();

    for (int t = 0; t < T; t++) {
        int cur = t & 1;
        bool havenext = (t + 1 < T);
        if (havenext) PREFETCH(t + 1)
#pragma unroll
        for (int kk = 0; kk < 16; kk++) {
            float4 a4 = *(const float4*)&As[cur][kk][ty * 4];
            float4 b4 = *(const float4*)&Bs[cur][kk][tx * 4];
            float a[4] = {a4.x, a4.y, a4.z, a4.w};
            float bb[4] = {b4.x, b4.y, b4.z, b4.w};
#pragma unroll
            for (int i = 0; i < 4; i++)
#pragma unroll
                for (int j = 0; j < 4; j++)
                    acc[i][j] = fmaf(a[i], bb[j], acc[i][j]);
        }
        if (havenext) {
            STORE(cur ^ 1)
            __syncthreads();
        }
    }
#pragma unroll
    for (int i = 0; i < 4; i++) {
        int gr = row0 + ty * 4 + i;
        if (gr >= N) continue;
        float dd = g_dinv[gr];
#pragma unroll
        for (int j = 0; j < 4; j++) {
            int gc = col0 + tx * 4 + j;
            if (gc < Mp)
                Hs[(size_t)gr * Mp + gc] = (gc < M) ? acc[i][j] * dd : 0.0f;
        }
    }
#undef PREFETCH
#undef STORE
}

// ---------------- coalesced CSR pull, sub-warp packed --------------------------
__global__ void k_pull(const float* __restrict__ Hs, const float* __restrict__ bias,
                       float* __restrict__ G, float* __restrict__ OUT,
                       int N, int M, int Mp, int nch4, int ngroups, int lg2gsz,
                       int mode,
                       const float* __restrict__ gam, const float* __restrict__ bet) {
    __shared__ float sm_s[F_MAX], sm_q[F_MAX];
    int tid = threadIdx.x;
    if (mode == 1) {
        for (int f = tid; f < F_MAX; f += blockDim.x) { sm_s[f] = 0.0f; sm_q[f] = 0.0f; }
        __syncthreads();
    }
    int gsz = 1 << lg2gsz;
    int epw = 32 >> lg2gsz;
    int lane = tid & 31;
    int sub = lane >> lg2gsz;
    int gw = (blockIdx.x * blockDim.x + tid) >> 5;
    int nw = (gridDim.x * blockDim.x) >> 5;
    int grp = (ngroups > 1) ? (gw % ngroups) : 0;
    int c = (lane & (gsz - 1)) + (grp << 5);
    bool act = c < nch4;
    int f0 = c << 2;
    float4 b4 = make_float4(0, 0, 0, 0);
    if (act) {
        b4.x = (f0 + 0 < M) ? bias[f0 + 0] : 0.0f;
        b4.y = (f0 + 1 < M) ? bias[f0 + 1] : 0.0f;
        b4.z = (f0 + 2 < M) ? bias[f0 + 2] : 0.0f;
        b4.w = (f0 + 3 < M) ? bias[f0 + 3] : 0.0f;
    }
    int wbase = gw / ngroups;
    int wstride = nw / ngroups;
    float4 ls = make_float4(0, 0, 0, 0), lq = make_float4(0, 0, 0, 0);

    for (int w = wbase; w * epw < N; w += wstride) {
        int d = w * epw + sub;
        bool vd = (d < N) && act;
        int beg = 0, end = 0;
        float dd = 0.0f;
        float4 acc = make_float4(0, 0, 0, 0);
        if (vd) {
            beg = g_rowptr[d];
            end = g_rowptr[d + 1];
            dd = g_dinv[d];
            acc = ((const float4*)(Hs + (size_t)d * Mp))[c];
        }
        int e = beg;
        for (; e + 7 < end; e += 8) {
            int s0 = g_csr[e], s1 = g_csr[e + 1], s2 = g_csr[e + 2], s3 = g_csr[e + 3];
            int s4 = g_csr[e + 4], s5 = g_csr[e + 5], s6 = g_csr[e + 6], s7 = g_csr[e + 7];
            float4 v0 = ((const float4*)(Hs + (size_t)s0 * Mp))[c];
            float4 v1 = ((const float4*)(Hs + (size_t)s1 * Mp))[c];
            float4 v2 = ((const float4*)(Hs + (size_t)s2 * Mp))[c];
            float4 v3 = ((const float4*)(Hs + (size_t)s3 * Mp))[c];
            float4 v4 = ((const float4*)(Hs + (size_t)s4 * Mp))[c];
            float4 v5 = ((const float4*)(Hs + (size_t)s5 * Mp))[c];
            float4 v6 = ((const float4*)(Hs + (size_t)s6 * Mp))[c];
            float4 v7 = ((const float4*)(Hs + (size_t)s7 * Mp))[c];
            acc.x += ((v0.x + v1.x) + (v2.x + v3.x)) + ((v4.x + v5.x) + (v6.x + v7.x));
            acc.y += ((v0.y + v1.y) + (v2.y + v3.y)) + ((v4.y + v5.y) + (v6.y + v7.y));
            acc.z += ((v0.z + v1.z) + (v2.z + v3.z)) + ((v4.z + v5.z) + (v6.z + v7.z));
            acc.w += ((v0.w + v1.w) + (v2.w + v3.w)) + ((v4.w + v5.w) + (v6.w + v7.w));
        }
        for (; e + 1 < end; e += 2) {
            int s0 = g_csr[e], s1 = g_csr[e + 1];
            float4 v0 = ((const float4*)(Hs + (size_t)s0 * Mp))[c];
            float4 v1 = ((const float4*)(Hs + (size_t)s1 * Mp))[c];
            acc.x += v0.x + v1.x; acc.y += v0.y + v1.y;
            acc.z += v0.z + v1.z; acc.w += v0.w + v1.w;
        }
        if (e < end) {
            int s0 = g_csr[e];
            float4 v0 = ((const float4*)(Hs + (size_t)s0 * Mp))[c];
            acc.x += v0.x; acc.y += v0.y; acc.z += v0.z; acc.w += v0.w;
        }
        float4 o;
        o.x = fmaf(dd, acc.x, b4.x);
        o.y = fmaf(dd, acc.y, b4.y);
        o.z = fmaf(dd, acc.z, b4.z);
        o.w = fmaf(dd, acc.w, b4.w);

        if (mode == 1) {
            if (vd) {
                ((float4*)(G + (size_t)d * Mp))[c] = o;
                float rx = fmaxf(o.x, 0.0f), ry = fmaxf(o.y, 0.0f);
                float rz = fmaxf(o.z, 0.0f), rw = fmaxf(o.w, 0.0f);
                ls.x += rx; ls.y += ry; ls.z += rz; ls.w += rw;
                lq.x += rx * rx; lq.y += ry * ry; lq.z += rz * rz; lq.w += rw * rw;
            }
        } else {
            bool vx = vd && (f0 + 0 < M), vy = vd && (f0 + 1 < M);
            bool vz = vd && (f0 + 2 < M), vw = vd && (f0 + 3 < M);
            float m = fmaxf(fmaxf(vx ? o.x : -1e30f, vy ? o.y : -1e30f),
                            fmaxf(vz ? o.z : -1e30f, vw ? o.w : -1e30f));
            for (int off = gsz >> 1; off; off >>= 1)
                m = fmaxf(m, __shfl_xor_sync(0xFFFFFFFFu, m, off, gsz));
            float s = (vx ? expf(o.x - m) : 0.0f) + (vy ? expf(o.y - m) : 0.0f)
                    + (vz ? expf(o.z - m) : 0.0f) + (vw ? expf(o.w - m) : 0.0f);
            for (int off = gsz >> 1; off; off >>= 1)
                s += __shfl_xor_sync(0xFFFFFFFFu, s, off, gsz);
            if (vd) {
                float lse = m + logf(s);
                float* orow = OUT + (size_t)d * M;
                if (vx) orow[f0 + 0] = o.x - lse;
                if (vy) orow[f0 + 1] = o.y - lse;
                if (vz) orow[f0 + 2] = o.z - lse;
                if (vw) orow[f0 + 3] = o.w - lse;
            }
        }
    }

    if (mode != 1) return;
    if (act) {
        atomicAdd(&sm_s[f0 + 0], ls.x); atomicAdd(&sm_q[f0 + 0], lq.x);
        atomicAdd(&sm_s[f0 + 1], ls.y); atomicAdd(&sm_q[f0 + 1], lq.y);
        atomicAdd(&sm_s[f0 + 2], ls.z); atomicAdd(&sm_q[f0 + 2], lq.z);
        atomicAdd(&sm_s[f0 + 3], ls.w); atomicAdd(&sm_q[f0 + 3], lq.w);
    }
    __syncthreads();
    for (int f = tid; f < M; f += blockDim.x) {
        atomicAdd(&g_sum[f], sm_s[f]);
        atomicAdd(&g_sumsq[f], sm_q[f]);
    }
    __threadfence();
    __syncthreads();
    __shared__ int is_last;
    if (tid == 0) {
        unsigned t = atomicAdd(&g_ticket, 1u);
        is_last = (t == gridDim.x - 1);
    }
    __syncthreads();
    if (is_last) {
        for (int f = tid; f < M; f += blockDim.x) {
            float mu = g_sum[f] / (float)N;
            float var = g_sumsq[f] / (float)N - mu * mu;
            float istd = rsqrtf(fmaxf(var, 0.0f) + 1e-5f);
            float sc = istd * gam[f];
            g_scale[f] = sc;
            g_shift[f] = bet[f] - mu * sc;
            g_sum[f] = 0.0f;
            g_sumsq[f] = 0.0f;
        }
        if (tid == 0) g_ticket = 0;
    }
}

// ---------------- orchestration ----------------
extern "C" void kernel_launch(void* const* d_in, const int* in_sizes, int n_in,
                              void* d_out, int out_size) {
    const float* x = (const float*)d_in[0];
    const void* ei = d_in[1];
    const float *W[5], *b[5], *gam[4], *bet[4];
    for (int i = 0; i < 5; i++) {
        W[i] = (const float*)d_in[2 + 2 * i];
        b[i] = (const float*)d_in[3 + 2 * i];
    }
    for (int i = 0; i < 4; i++) {
        gam[i] = (const float*)d_in[12 + 2 * i];
        bet[i] = (const float*)d_in[13 + 2 * i];
    }
    int dims[6];
    for (int i = 0; i < 5; i++) dims[i + 1] = in_sizes[3 + 2 * i];
    dims[0] = in_sizes[2] / dims[1];
    int N = in_sizes[0] / dims[0];
    int E = in_sizes[1] / 2;

    float *bufH, *bufG[2];
    cudaGetSymbolAddress((void**)&bufH, g_bufH);
    cudaGetSymbolAddress((void**)&bufG[0], g_bufG0);
    cudaGetSymbolAddress((void**)&bufG[1], g_bufG1);

    k_pre<<<PRE_BLOCKS, 256>>>(ei, N, E);

    const float* in = x;
    int Kp = dims[0];
    int transform = 0;
    for (int l = 0; l < 5; l++) {
        int K = dims[l], M = dims[l + 1];
        int Mp = (M + 3) & ~3;
        float* G = bufG[l & 1];

        int colT64 = (Mp + 63) / 64;
        int rows128 = (N + 127) / 128;
        if (rows128 * colT64 >= 148) {
            dim3 grid(colT64, rows128);
            k_gemm128<<<grid, 256>>>(in, W[l], bufH, N, K, M, Kp, Mp, transform);
        } else {
            dim3 grid(colT64, (N + 63) / 64);
            k_gemm64<<<grid, 256>>>(in, W[l], bufH, N, K, M, Kp, Mp, transform);
        }

        int nch4 = Mp >> 2;
        int ngroups, lg2;
        if (nch4 > 32)      { ngroups = (nch4 + 31) >> 5; lg2 = 5; }
        else if (nch4 > 16) { ngroups = 1; lg2 = 5; }
        else if (nch4 > 8)  { ngroups = 1; lg2 = 4; }
        else if (nch4 > 4)  { ngroups = 1; lg2 = 3; }
        else if (nch4 > 2)  { ngroups = 1; lg2 = 2; }
        else                { ngroups = 1; lg2 = 1; }
        int mode = (l < 4) ? 1 : 2;
        k_pull<<<1184, 256>>>(bufH, b[l], G, (float*)d_out, N, M, Mp, nch4,
                              ngroups, lg2, mode,
                              (l < 4) ? gam[l] : b[l], (l < 4) ? bet[l] : b[l]);

        if (l < 4) {
            in = G;
            Kp = Mp;
            transform = 1;
        }
    }
}

// round 16
// speedup vs baseline: 1.1788x; 1.0248x over previous
#include <cuda_runtime.h>
#include <math.h>

#define N_MAX 16384
#define F_MAX 256
#define E_MAX 524288
#define PRE_BLOCKS 148

// ---------------- scratch (device globals: no allocation allowed) ----------------
__device__ __align__(16) float g_bufH[N_MAX * F_MAX];   // Hs = h * dinv[row]
__device__ __align__(16) float g_bufG0[N_MAX * F_MAX];  // agg ping
__device__ __align__(16) float g_bufG1[N_MAX * F_MAX];  // agg pong
__device__ float g_dinv[N_MAX];
__device__ int   g_cin[N_MAX];
__device__ int   g_rowptr[N_MAX + 1];
__device__ int   g_fill[N_MAX];
__device__ int   g_csr[E_MAX];
__device__ float g_sum[F_MAX], g_sumsq[F_MAX];
__device__ float g_scale[F_MAX], g_shift[F_MAX];
__device__ unsigned g_ticket;
__device__ unsigned g_bar;   // zero-init; reset by GEMM launches

// ---------------- vectorized global reduction -------------------------------
__device__ __forceinline__ void red4(float4* p, float x, float y, float z, float w) {
    asm volatile("red.global.add.v4.f32 [%0], {%1,%2,%3,%4};"
                 :: "l"(p), "f"(x), "f"(y), "f"(z), "f"(w) : "memory");
}

// ---------------- fused preamble ----------------
__device__ __forceinline__ void gbar(unsigned target) {
    __syncthreads();
    if (threadIdx.x == 0) {
        __threadfence();
        atomicAdd(&g_bar, 1u);
        while (*(volatile unsigned*)&g_bar < target) __nanosleep(64);
        __threadfence();
    }
    __syncthreads();
}

__device__ __forceinline__ void edge_sd_z(const void* ei, int z, int e, int E,
                                          int& s, int& d) {
    if (z) {
        const long long* p = (const long long*)ei;
        s = (int)p[e];
        d = (int)p[(long long)E + e];
    } else {
        const int* p = (const int*)ei;
        s = p[e];
        d = p[E + e];
    }
}

__global__ void k_pre(const void* __restrict__ ei, int N, int E) {
    const int* eip = (const int*)ei;
    int z = 1;
#pragma unroll
    for (int t = 0; t < 32; t++) z &= (eip[2 * t + 1] == 0);

    int tid = threadIdx.x;
    int gt = blockIdx.x * blockDim.x + tid;
    int nthr = gridDim.x * blockDim.x;

    for (int i = gt; i < N; i += nthr) { g_cin[i] = 0; g_fill[i] = 0; }
    if (gt < F_MAX) { g_sum[gt] = 0.0f; g_sumsq[gt] = 0.0f; }
    if (gt == 0) g_ticket = 0;
    gbar(1 * PRE_BLOCKS);

    for (int e = gt; e < E; e += nthr) {
        int s, d;
        edge_sd_z(ei, z, e, E, s, d);
        atomicAdd(&g_cin[d], 1);
    }
    gbar(2 * PRE_BLOCKS);

    if (blockIdx.x == 0) {
        __shared__ int wsum[8];
        int chunk = (N + 255) >> 8;
        int t0 = tid * chunk, t1 = min(N, t0 + chunk);
        int s = 0;
        for (int i = t0; i < t1; i++) {
            int c = g_cin[i];
            g_dinv[i] = rsqrtf((float)c + 1.0f);
            s += c;
        }
        int lane = tid & 31, wid = tid >> 5;
        int v = s;
#pragma unroll
        for (int o = 1; o < 32; o <<= 1) {
            int u = __shfl_up_sync(0xFFFFFFFFu, v, o);
            if (lane >= o) v += u;
        }
        if (lane == 31) wsum[wid] = v;
        __syncthreads();
        if (wid == 0 && lane < 8) {
            int w = wsum[lane];
#pragma unroll
            for (int o = 1; o < 8; o <<= 1) {
                int u = __shfl_up_sync(0xFFu, w, o);
                if (lane >= o) w += u;
            }
            wsum[lane] = w;
        }
        __syncthreads();
        int run = v - s + (wid > 0 ? wsum[wid - 1] : 0);
        for (int i = t0; i < t1; i++) {
            g_rowptr[i] = run;
            run += g_cin[i];
        }
        if (t0 < N && t1 == N) g_rowptr[N] = run;
    }
    gbar(3 * PRE_BLOCKS);

    for (int e = gt; e < E; e += nthr) {
        int s, d;
        edge_sd_z(ei, z, e, E, s, d);
        int pos = g_rowptr[d] + atomicAdd(&g_fill[d], 1);
        g_csr[pos] = s;
    }
}

// ---------------- zero Hs (for split-K red accumulation) -----------------------
__global__ void k_zeroH(float4* Hs, size_t total4) {
    size_t i = (size_t)blockIdx.x * blockDim.x + threadIdx.x;
    size_t stride = (size_t)gridDim.x * blockDim.x;
    float4 z = make_float4(0, 0, 0, 0);
    for (; i < total4; i += stride) Hs[i] = z;
}

// ---------------- GEMM 128x64 tile (8x4 micro), double-buffered, FFMA2, splitK -
__global__ __launch_bounds__(256) void k_gemm128(
        const float* __restrict__ A, const float* __restrict__ B,
        float* __restrict__ Hs,
        int N, int K, int M, int Kp, int Mp, int transform) {
    if (threadIdx.x == 0 && blockIdx.x == 0 && blockIdx.y == 0 && blockIdx.z == 0)
        g_bar = 0;
    __shared__ __align__(16) float As[2][16][132];
    __shared__ __align__(16) float Bs[2][16][68];
    int tid = threadIdx.x;
    int tx = tid & 15, ty = tid >> 4;
    int row0 = blockIdx.y * 128, col0 = blockIdx.x * 64;
    unsigned long long acc2[4][4] = {};

    int T_all = (K + 15) >> 4;
    int per = (T_all + gridDim.z - 1) / gridDim.z;
    int t0 = blockIdx.z * per;
    int t1 = min(T_all, t0 + per);

    int ar = tid >> 1;
    int c8 = (tid & 1) * 8;
    int agr = row0 + ar;
    int br = tid >> 4;
    int bc = (tid & 15) * 4;

    float4 pa0, pa1;
    float pb[4];

#define PREFETCH(t)                                                              \
    {                                                                            \
        int k0 = (t) << 4;                                                       \
        pa0 = make_float4(0, 0, 0, 0);                                           \
        pa1 = make_float4(0, 0, 0, 0);                                           \
        if (agr < N) {                                                           \
            pa0 = *(const float4*)(A + (size_t)agr * Kp + k0 + c8);              \
            pa1 = *(const float4*)(A + (size_t)agr * Kp + k0 + c8 + 4);          \
            if (transform) {                                                     \
                pa0.x = fmaf(fmaxf(pa0.x, 0.0f), g_scale[k0 + c8 + 0], g_shift[k0 + c8 + 0]); \
                pa0.y = fmaf(fmaxf(pa0.y, 0.0f), g_scale[k0 + c8 + 1], g_shift[k0 + c8 + 1]); \
                pa0.z = fmaf(fmaxf(pa0.z, 0.0f), g_scale[k0 + c8 + 2], g_shift[k0 + c8 + 2]); \
                pa0.w = fmaf(fmaxf(pa0.w, 0.0f), g_scale[k0 + c8 + 3], g_shift[k0 + c8 + 3]); \
                pa1.x = fmaf(fmaxf(pa1.x, 0.0f), g_scale[k0 + c8 + 4], g_shift[k0 + c8 + 4]); \
                pa1.y = fmaf(fmaxf(pa1.y, 0.0f), g_scale[k0 + c8 + 5], g_shift[k0 + c8 + 5]); \
                pa1.z = fmaf(fmaxf(pa1.z, 0.0f), g_scale[k0 + c8 + 6], g_shift[k0 + c8 + 6]); \
                pa1.w = fmaf(fmaxf(pa1.w, 0.0f), g_scale[k0 + c8 + 7], g_shift[k0 + c8 + 7]); \
            }                                                                    \
        }                                                                        \
        int gk = k0 + br;                                                        \
        _Pragma("unroll")                                                        \
        for (int i = 0; i < 4; i++) {                                            \
            int gc = col0 + bc + i;                                              \
            pb[i] = (gk < K && gc < M) ? B[(size_t)gk * M + gc] : 0.0f;          \
        }                                                                        \
    }

#define STORE(buf)                                                               \
    {                                                                            \
        As[buf][c8 + 0][ar] = pa0.x;                                             \
        As[buf][c8 + 1][ar] = pa0.y;                                             \
        As[buf][c8 + 2][ar] = pa0.z;                                             \
        As[buf][c8 + 3][ar] = pa0.w;                                             \
        As[buf][c8 + 4][ar] = pa1.x;                                             \
        As[buf][c8 + 5][ar] = pa1.y;                                             \
        As[buf][c8 + 6][ar] = pa1.z;                                             \
        As[buf][c8 + 7][ar] = pa1.w;                                             \
        *(float4*)&Bs[buf][br][bc] = make_float4(pb[0], pb[1], pb[2], pb[3]);    \
    }

    PREFETCH(t0)
    STORE(0)
    __syncthreads();

    for (int t = t0; t < t1; t++) {
        int cur = (t - t0) & 1;
        bool havenext = (t + 1 < t1);
        if (havenext) PREFETCH(t + 1)
#pragma unroll
        for (int kk = 0; kk < 16; kk++) {
            double2 a01 = *(const double2*)&As[cur][kk][ty * 8];
            double2 a23 = *(const double2*)&As[cur][kk][ty * 8 + 4];
            unsigned long long ap[4];
            ap[0] = __double_as_longlong(a01.x);
            ap[1] = __double_as_longlong(a01.y);
            ap[2] = __double_as_longlong(a23.x);
            ap[3] = __double_as_longlong(a23.y);
            float4 b4 = *(const float4*)&Bs[cur][kk][tx * 4];
            unsigned long long bd[4];
            asm("mov.b64 %0, {%1,%1};" : "=l"(bd[0]) : "f"(b4.x));
            asm("mov.b64 %0, {%1,%1};" : "=l"(bd[1]) : "f"(b4.y));
            asm("mov.b64 %0, {%1,%1};" : "=l"(bd[2]) : "f"(b4.z));
            asm("mov.b64 %0, {%1,%1};" : "=l"(bd[3]) : "f"(b4.w));
#pragma unroll
            for (int p = 0; p < 4; p++)
#pragma unroll
                for (int j = 0; j < 4; j++)
                    asm("fma.rn.f32x2 %0, %1, %2, %0;"
                        : "+l"(acc2[p][j]) : "l"(ap[p]), "l"(bd[j]));
        }
        if (havenext) {
            STORE(cur ^ 1)
            __syncthreads();
        }
    }
    // epilogue
    int gc4 = col0 + tx * 4;
    bool inb = gc4 < Mp;
#pragma unroll
    for (int p = 0; p < 4; p++) {
        int gr0 = row0 + ty * 8 + 2 * p;
        int gr1 = gr0 + 1;
        float lo[4], hi[4];
#pragma unroll
        for (int j = 0; j < 4; j++) {
            asm("mov.b64 {%0,%1}, %2;" : "=f"(lo[j]), "=f"(hi[j]) : "l"(acc2[p][j]));
            if (gc4 + j >= M) { lo[j] = 0.0f; hi[j] = 0.0f; }
        }
        if (gridDim.z == 1) {
            if (inb) {
                if (gr0 < N) {
                    float dd = g_dinv[gr0];
                    *(float4*)(Hs + (size_t)gr0 * Mp + gc4) =
                        make_float4(lo[0] * dd, lo[1] * dd, lo[2] * dd, lo[3] * dd);
                }
                if (gr1 < N) {
                    float dd = g_dinv[gr1];
                    *(float4*)(Hs + (size_t)gr1 * Mp + gc4) =
                        make_float4(hi[0] * dd, hi[1] * dd, hi[2] * dd, hi[3] * dd);
                }
            }
        } else {
            if (inb) {
                if (gr0 < N) {
                    float dd = g_dinv[gr0];
                    red4((float4*)(Hs + (size_t)gr0 * Mp + gc4),
                         lo[0] * dd, lo[1] * dd, lo[2] * dd, lo[3] * dd);
                }
                if (gr1 < N) {
                    float dd = g_dinv[gr1];
                    red4((float4*)(Hs + (size_t)gr1 * Mp + gc4),
                         hi[0] * dd, hi[1] * dd, hi[2] * dd, hi[3] * dd);
                }
            }
        }
    }
#undef PREFETCH
#undef STORE
}

// ---------------- GEMM 64x64 tile (4x4 micro), double-buffered, FFMA2 ----------
__global__ __launch_bounds__(256) void k_gemm64(
        const float* __restrict__ A, const float* __restrict__ B,
        float* __restrict__ Hs,
        int N, int K, int M, int Kp, int Mp, int transform) {
    if (threadIdx.x == 0 && blockIdx.x == 0 && blockIdx.y == 0) g_bar = 0;
    __shared__ __align__(16) float As[2][16][68];
    __shared__ __align__(16) float Bs[2][16][68];
    int tid = threadIdx.x;
    int tx = tid & 15, ty = tid >> 4;
    int row0 = blockIdx.y * 64, col0 = blockIdx.x * 64;
    unsigned long long acc2[2][4] = {};

    int T = (K + 15) >> 4;

    int ar = tid >> 2;
    int kc = (tid & 3) * 4;
    int agr = row0 + ar;
    int br = tid >> 4;
    int bc = (tid & 15) * 4;

    float4 pa;
    float pb[4];

#define PREFETCH(t)                                                              \
    {                                                                            \
        int k0 = (t) << 4;                                                       \
        pa = make_float4(0, 0, 0, 0);                                            \
        if (agr < N) {                                                           \
            pa = *(const float4*)(A + (size_t)agr * Kp + k0 + kc);               \
            if (transform) {                                                     \
                pa.x = fmaf(fmaxf(pa.x, 0.0f), g_scale[k0 + kc + 0], g_shift[k0 + kc + 0]); \
                pa.y = fmaf(fmaxf(pa.y, 0.0f), g_scale[k0 + kc + 1], g_shift[k0 + kc + 1]); \
                pa.z = fmaf(fmaxf(pa.z, 0.0f), g_scale[k0 + kc + 2], g_shift[k0 + kc + 2]); \
                pa.w = fmaf(fmaxf(pa.w, 0.0f), g_scale[k0 + kc + 3], g_shift[k0 + kc + 3]); \
            }                                                                    \
        }                                                                        \
        int gk = k0 + br;                                                        \
        _Pragma("unroll")                                                        \
        for (int i = 0; i < 4; i++) {                                            \
            int gc = col0 + bc + i;                                              \
            pb[i] = (gk < K && gc < M) ? B[(size_t)gk * M + gc] : 0.0f;          \
        }                                                                        \
    }

#define STORE(buf)                                                               \
    {                                                                            \
        As[buf][kc + 0][ar] = pa.x;                                              \
        As[buf][kc + 1][ar] = pa.y;                                              \
        As[buf][kc + 2][ar] = pa.z;                                              \
        As[buf][kc + 3][ar] = pa.w;                                              \
        *(float4*)&Bs[buf][br][bc] = make_float4(pb[0], pb[1], pb[2], pb[3]);    \
    }

    PREFETCH(0)
    STORE(0)
    __syncthreads();

    for (int t = 0; t < T; t++) {
        int cur = t & 1;
        bool havenext = (t + 1 < T);
        if (havenext) PREFETCH(t + 1)
#pragma unroll
        for (int kk = 0; kk < 16; kk++) {
            double2 a01 = *(const double2*)&As[cur][kk][ty * 4];
            unsigned long long ap[2];
            ap[0] = __double_as_longlong(a01.x);
            ap[1] = __double_as_longlong(a01.y);
            float4 b4 = *(const float4*)&Bs[cur][kk][tx * 4];
            unsigned long long bd[4];
            asm("mov.b64 %0, {%1,%1};" : "=l"(bd[0]) : "f"(b4.x));
            asm("mov.b64 %0, {%1,%1};" : "=l"(bd[1]) : "f"(b4.y));
            asm("mov.b64 %0, {%1,%1};" : "=l"(bd[2]) : "f"(b4.z));
            asm("mov.b64 %0, {%1,%1};" : "=l"(bd[3]) : "f"(b4.w));
#pragma unroll
            for (int p = 0; p < 2; p++)
#pragma unroll
                for (int j = 0; j < 4; j++)
                    asm("fma.rn.f32x2 %0, %1, %2, %0;"
                        : "+l"(acc2[p][j]) : "l"(ap[p]), "l"(bd[j]));
        }
        if (havenext) {
            STORE(cur ^ 1)
            __syncthreads();
        }
    }
#pragma unroll
    for (int p = 0; p < 2; p++) {
        int gr0 = row0 + ty * 4 + 2 * p;
        int gr1 = gr0 + 1;
#pragma unroll
        for (int j = 0; j < 4; j++) {
            float lo, hi;
            asm("mov.b64 {%0,%1}, %2;" : "=f"(lo), "=f"(hi) : "l"(acc2[p][j]));
            int gc = col0 + tx * 4 + j;
            if (gc < Mp) {
                if (gr0 < N) {
                    float dd = g_dinv[gr0];
                    Hs[(size_t)gr0 * Mp + gc] = (gc < M) ? lo * dd : 0.0f;
                }
                if (gr1 < N) {
                    float dd = g_dinv[gr1];
                    Hs[(size_t)gr1 * Mp + gc] = (gc < M) ? hi * dd : 0.0f;
                }
            }
        }
    }
#undef PREFETCH
#undef STORE
}

// ---------------- coalesced CSR pull, sub-warp packed --------------------------
__global__ void k_pull(const float* __restrict__ Hs, const float* __restrict__ bias,
                       float* __restrict__ G, float* __restrict__ OUT,
                       int N, int M, int Mp, int nch4, int ngroups, int lg2gsz,
                       int mode,
                       const float* __restrict__ gam, const float* __restrict__ bet) {
    __shared__ float sm_s[F_MAX], sm_q[F_MAX];
    int tid = threadIdx.x;
    if (mode == 1) {
        for (int f = tid; f < F_MAX; f += blockDim.x) { sm_s[f] = 0.0f; sm_q[f] = 0.0f; }
        __syncthreads();
    }
    int gsz = 1 << lg2gsz;
    int epw = 32 >> lg2gsz;
    int lane = tid & 31;
    int sub = lane >> lg2gsz;
    int gw = (blockIdx.x * blockDim.x + tid) >> 5;
    int nw = (gridDim.x * blockDim.x) >> 5;
    int grp = (ngroups > 1) ? (gw % ngroups) : 0;
    int c = (lane & (gsz - 1)) + (grp << 5);
    bool act = c < nch4;
    int f0 = c << 2;
    float4 b4 = make_float4(0, 0, 0, 0);
    if (act) {
        b4.x = (f0 + 0 < M) ? bias[f0 + 0] : 0.0f;
        b4.y = (f0 + 1 < M) ? bias[f0 + 1] : 0.0f;
        b4.z = (f0 + 2 < M) ? bias[f0 + 2] : 0.0f;
        b4.w = (f0 + 3 < M) ? bias[f0 + 3] : 0.0f;
    }
    int wbase = gw / ngroups;
    int wstride = nw / ngroups;
    float4 ls = make_float4(0, 0, 0, 0), lq = make_float4(0, 0, 0, 0);

    for (int w = wbase; w * epw < N; w += wstride) {
        int d = w * epw + sub;
        bool vd = (d < N) && act;
        int beg = 0, end = 0;
        float dd = 0.0f;
        float4 acc = make_float4(0, 0, 0, 0);
        if (vd) {
            beg = g_rowptr[d];
            end = g_rowptr[d + 1];
            dd = g_dinv[d];
            acc = ((const float4*)(Hs + (size_t)d * Mp))[c];
        }
        int e = beg;
        for (; e + 7 < end; e += 8) {
            int s0 = g_csr[e], s1 = g_csr[e + 1], s2 = g_csr[e + 2], s3 = g_csr[e + 3];
            int s4 = g_csr[e + 4], s5 = g_csr[e + 5], s6 = g_csr[e + 6], s7 = g_csr[e + 7];
            float4 v0 = ((const float4*)(Hs + (size_t)s0 * Mp))[c];
            float4 v1 = ((const float4*)(Hs + (size_t)s1 * Mp))[c];
            float4 v2 = ((const float4*)(Hs + (size_t)s2 * Mp))[c];
            float4 v3 = ((const float4*)(Hs + (size_t)s3 * Mp))[c];
            float4 v4 = ((const float4*)(Hs + (size_t)s4 * Mp))[c];
            float4 v5 = ((const float4*)(Hs + (size_t)s5 * Mp))[c];
            float4 v6 = ((const float4*)(Hs + (size_t)s6 * Mp))[c];
            float4 v7 = ((const float4*)(Hs + (size_t)s7 * Mp))[c];
            acc.x += ((v0.x + v1.x) + (v2.x + v3.x)) + ((v4.x + v5.x) + (v6.x + v7.x));
            acc.y += ((v0.y + v1.y) + (v2.y + v3.y)) + ((v4.y + v5.y) + (v6.y + v7.y));
            acc.z += ((v0.z + v1.z) + (v2.z + v3.z)) + ((v4.z + v5.z) + (v6.z + v7.z));
            acc.w += ((v0.w + v1.w) + (v2.w + v3.w)) + ((v4.w + v5.w) + (v6.w + v7.w));
        }
        for (; e + 1 < end; e += 2) {
            int s0 = g_csr[e], s1 = g_csr[e + 1];
            float4 v0 = ((const float4*)(Hs + (size_t)s0 * Mp))[c];
            float4 v1 = ((const float4*)(Hs + (size_t)s1 * Mp))[c];
            acc.x += v0.x + v1.x; acc.y += v0.y + v1.y;
            acc.z += v0.z + v1.z; acc.w += v0.w + v1.w;
        }
        if (e < end) {
            int s0 = g_csr[e];
            float4 v0 = ((const float4*)(Hs + (size_t)s0 * Mp))[c];
            acc.x += v0.x; acc.y += v0.y; acc.z += v0.z; acc.w += v0.w;
        }
        float4 o;
        o.x = fmaf(dd, acc.x, b4.x);
        o.y = fmaf(dd, acc.y, b4.y);
        o.z = fmaf(dd, acc.z, b4.z);
        o.w = fmaf(dd, acc.w, b4.w);

        if (mode == 1) {
            if (vd) {
                ((float4*)(G + (size_t)d * Mp))[c] = o;
                float rx = fmaxf(o.x, 0.0f), ry = fmaxf(o.y, 0.0f);
                float rz = fmaxf(o.z, 0.0f), rw = fmaxf(o.w, 0.0f);
                ls.x += rx; ls.y += ry; ls.z += rz; ls.w += rw;
                lq.x += rx * rx; lq.y += ry * ry; lq.z += rz * rz; lq.w += rw * rw;
            }
        } else {
            bool vx = vd && (f0 + 0 < M), vy = vd && (f0 + 1 < M);
            bool vz = vd && (f0 + 2 < M), vw = vd && (f0 + 3 < M);
            float m = fmaxf(fmaxf(vx ? o.x : -1e30f, vy ? o.y : -1e30f),
                            fmaxf(vz ? o.z : -1e30f, vw ? o.w : -1e30f));
            for (int off = gsz >> 1; off; off >>= 1)
                m = fmaxf(m, __shfl_xor_sync(0xFFFFFFFFu, m, off, gsz));
            float s = (vx ? expf(o.x - m) : 0.0f) + (vy ? expf(o.y - m) : 0.0f)
                    + (vz ? expf(o.z - m) : 0.0f) + (vw ? expf(o.w - m) : 0.0f);
            for (int off = gsz >> 1; off; off >>= 1)
                s += __shfl_xor_sync(0xFFFFFFFFu, s, off, gsz);
            if (vd) {
                float lse = m + logf(s);
                float* orow = OUT + (size_t)d * M;
                if (vx) orow[f0 + 0] = o.x - lse;
                if (vy) orow[f0 + 1] = o.y - lse;
                if (vz) orow[f0 + 2] = o.z - lse;
                if (vw) orow[f0 + 3] = o.w - lse;
            }
        }
    }

    if (mode != 1) return;
    if (act) {
        atomicAdd(&sm_s[f0 + 0], ls.x); atomicAdd(&sm_q[f0 + 0], lq.x);
        atomicAdd(&sm_s[f0 + 1], ls.y); atomicAdd(&sm_q[f0 + 1], lq.y);
        atomicAdd(&sm_s[f0 + 2], ls.z); atomicAdd(&sm_q[f0 + 2], lq.z);
        atomicAdd(&sm_s[f0 + 3], ls.w); atomicAdd(&sm_q[f0 + 3], lq.w);
    }
    __syncthreads();
    for (int f = tid; f < M; f += blockDim.x) {
        atomicAdd(&g_sum[f], sm_s[f]);
        atomicAdd(&g_sumsq[f], sm_q[f]);
    }
    __threadfence();
    __syncthreads();
    __shared__ int is_last;
    if (tid == 0) {
        unsigned t = atomicAdd(&g_ticket, 1u);
        is_last = (t == gridDim.x - 1);
    }
    __syncthreads();
    if (is_last) {
        for (int f = tid; f < M; f += blockDim.x) {
            float mu = g_sum[f] / (float)N;
            float var = g_sumsq[f] / (float)N - mu * mu;
            float istd = rsqrtf(fmaxf(var, 0.0f) + 1e-5f);
            float sc = istd * gam[f];
            g_scale[f] = sc;
            g_shift[f] = bet[f] - mu * sc;
            g_sum[f] = 0.0f;
            g_sumsq[f] = 0.0f;
        }
        if (tid == 0) g_ticket = 0;
    }
}

// ---------------- orchestration ----------------
extern "C" void kernel_launch(void* const* d_in, const int* in_sizes, int n_in,
                              void* d_out, int out_size) {
    const float* x = (const float*)d_in[0];
    const void* ei = d_in[1];
    const float *W[5], *b[5], *gam[4], *bet[4];
    for (int i = 0; i < 5; i++) {
        W[i] = (const float*)d_in[2 + 2 * i];
        b[i] = (const float*)d_in[3 + 2 * i];
    }
    for (int i = 0; i < 4; i++) {
        gam[i] = (const float*)d_in[12 + 2 * i];
        bet[i] = (const float*)d_in[13 + 2 * i];
    }
    int dims[6];
    for (int i = 0; i < 5; i++) dims[i + 1] = in_sizes[3 + 2 * i];
    dims[0] = in_sizes[2] / dims[1];
    int N = in_sizes[0] / dims[0];
    int E = in_sizes[1] / 2;

    float *bufH, *bufG[2];
    cudaGetSymbolAddress((void**)&bufH, g_bufH);
    cudaGetSymbolAddress((void**)&bufG[0], g_bufG0);
    cudaGetSymbolAddress((void**)&bufG[1], g_bufG1);

    k_pre<<<PRE_BLOCKS, 256>>>(ei, N, E);

    const float* in = x;
    int Kp = dims[0];
    int transform = 0;
    for (int l = 0; l < 5; l++) {
        int K = dims[l], M = dims[l + 1];
        int Mp = (M + 3) & ~3;
        float* G = bufG[l & 1];

        int colT64 = (Mp + 63) / 64;
        int rows128 = (N + 127) / 128;
        int blocks2d = rows128 * colT64;
        int T_all = (K + 15) / 16;
        if (blocks2d >= 148) {
            int ksplit = (blocks2d < 280 && T_all >= 2) ? 2 : 1;
            if (ksplit == 2)
                k_zeroH<<<592, 256>>>((float4*)bufH, (size_t)N * Mp / 4);
            dim3 grid(colT64, rows128, ksplit);
            k_gemm128<<<grid, 256>>>(in, W[l], bufH, N, K, M, Kp, Mp, transform);
        } else {
            dim3 grid(colT64, (N + 63) / 64);
            k_gemm64<<<grid, 256>>>(in, W[l], bufH, N, K, M, Kp, Mp, transform);
        }

        int nch4 = Mp >> 2;
        int ngroups, lg2;
        if (nch4 > 32)      { ngroups = (nch4 + 31) >> 5; lg2 = 5; }
        else if (nch4 > 16) { ngroups = 1; lg2 = 5; }
        else if (nch4 > 8)  { ngroups = 1; lg2 = 4; }
        else if (nch4 > 4)  { ngroups = 1; lg2 = 3; }
        else if (nch4 > 2)  { ngroups = 1; lg2 = 2; }
        else                { ngroups = 1; lg2 = 1; }
        int mode = (l < 4) ? 1 : 2;
        k_pull<<<1184, 256>>>(bufH, b[l], G, (float*)d_out, N, M, Mp, nch4,
                              ngroups, lg2, mode,
                              (l < 4) ? gam[l] : b[l], (l < 4) ? bet[l] : b[l]);

        if (l < 4) {
            in = G;
            Kp = Mp;
            transform = 1;
        }
    }
}